// round 8
// baseline (speedup 1.0000x reference)
#include <cuda_runtime.h>
#include <cuda_fp16.h>
#include <math.h>
#include <stdint.h>

#define T_TOK 8192
#define H_DIM 2048
#define I_DIM 1408
#define E_NUM 16
#define TOPK  2
#define NSLOT (T_TOK * TOPK)

#define BM 128
#define BN 64
#define BK 64                 // halves per K-slab (128 B/row)
#define SROW2 72              // padded halves per smem row (144 B)
#define A_BYTES (128 * SROW2 * 2)       // 18432
#define B_BYTES (64  * SROW2 * 2)       // 9216
#define STG1_B (A_BYTES + 2 * B_BYTES)  // 36864
#define STG2_B (A_BYTES + B_BYTES)      // 27648

// ----------------------------- device scratch --------------------------------
__device__ __half g_xh [(size_t)T_TOK * H_DIM];
__device__ __half g_w1h[(size_t)E_NUM * I_DIM * H_DIM];
__device__ __half g_uph[(size_t)E_NUM * I_DIM * H_DIM];
__device__ __half g_w2h[(size_t)E_NUM * H_DIM * I_DIM];
__device__ __half g_h  [(size_t)NSLOT * I_DIM];
__device__ float  g_o2 [(size_t)NSLOT * H_DIM];
__device__ int    g_top2[T_TOK * 2];
__device__ float  g_wts [T_TOK * 2];
__device__ int    g_off [E_NUM + 1];
__device__ int    g_tok [NSLOT];
__device__ float  g_slotw[NSLOT];
__device__ int    g_slot[T_TOK * 2];

// ----------------------------- helpers ---------------------------------------
__device__ __forceinline__ uint32_t smem_u32(const void* p) {
    uint32_t a;
    asm("{ .reg .u64 t; cvta.to.shared.u64 t, %1; cvt.u32.u64 %0, t; }" : "=r"(a) : "l"(p));
    return a;
}
__device__ __forceinline__ void cp16(uint32_t dst, const void* src) {
    asm volatile("cp.async.cg.shared.global [%0], [%1], 16;"
                 :: "r"(dst), "l"(__cvta_generic_to_global(src)) : "memory");
}
#define CP_COMMIT() asm volatile("cp.async.commit_group;" ::: "memory")
#define CP_WAIT(n)  asm volatile("cp.async.wait_group %0;" :: "n"(n) : "memory")

#define MMA_F16(d, a, b)                                                       \
    asm volatile("mma.sync.aligned.m16n8k16.row.col.f32.f16.f16.f32 "          \
        "{%0,%1,%2,%3}, {%4,%5,%6,%7}, {%8,%9}, {%0,%1,%2,%3};"                \
        : "+f"((d)[0]), "+f"((d)[1]), "+f"((d)[2]), "+f"((d)[3])               \
        : "r"((a)[0]), "r"((a)[1]), "r"((a)[2]), "r"((a)[3]),                  \
          "r"((b)[0]), "r"((b)[1]))

#define LDSM_X4(r, addr)                                                       \
    asm volatile("ldmatrix.sync.aligned.m8n8.x4.shared.b16 {%0,%1,%2,%3}, [%4];" \
        : "=r"((r)[0]), "=r"((r)[1]), "=r"((r)[2]), "=r"((r)[3]) : "r"(addr))

__device__ __forceinline__ float silu_mul(float a, float u) {
    return (a / (1.f + __expf(-a))) * u;
}

// ----------------------------- fp16 weight conversion ------------------------
__global__ void f2h_all(const float4* __restrict__ w1, const float4* __restrict__ up,
                        const float4* __restrict__ w2) {
    const long n4 = (long)E_NUM * I_DIM * H_DIM / 4;
    long i = blockIdx.x * (long)blockDim.x + threadIdx.x;
    long stride = (long)gridDim.x * blockDim.x;
    for (; i < 3 * n4; i += stride) {
        const float4* src;
        __half* dsth;
        long j;
        if (i < n4)          { src = w1 + i;            dsth = g_w1h; j = i; }
        else if (i < 2 * n4) { src = up + (i - n4);     dsth = g_uph; j = i - n4; }
        else                 { src = w2 + (i - 2 * n4); dsth = g_w2h; j = i - 2 * n4; }
        float4 v = *src;
        __half2 h01 = __floats2half2_rn(v.x, v.y);
        __half2 h23 = __floats2half2_rn(v.z, v.w);
        uint2 u;
        u.x = *(uint32_t*)&h01;
        u.y = *(uint32_t*)&h23;
        *(uint2*)(dsth + j * 4) = u;
    }
}

// ----------------------------- gate (+ x -> fp16) ----------------------------
__global__ __launch_bounds__(256)
void gate_kernel(const float* __restrict__ x, const float* __restrict__ gw) {
    extern __shared__ float sgw[];
    int tid = threadIdx.x;
    for (int i = tid; i < E_NUM * H_DIM / 4; i += 256)
        ((float4*)sgw)[i] = ((const float4*)gw)[i];
    __syncthreads();

    int warp = tid >> 5, lane = tid & 31;
#pragma unroll
    for (int i = 0; i < 4; i++) {
        int t = blockIdx.x * 32 + warp * 4 + i;
        const float* xr = x + (size_t)t * H_DIM;
        float acc[E_NUM];
#pragma unroll
        for (int e = 0; e < E_NUM; e++) acc[e] = 0.f;
        for (int k = lane * 2; k < H_DIM; k += 64) {
            float2 xv = *(const float2*)(xr + k);
            __half2 hv = __floats2half2_rn(xv.x, xv.y);
            *(__half2*)(g_xh + (size_t)t * H_DIM + k) = hv;
#pragma unroll
            for (int e = 0; e < E_NUM; e++) {
                float2 g = *(const float2*)(sgw + e * H_DIM + k);
                acc[e] += xv.x * g.x + xv.y * g.y;
            }
        }
#pragma unroll
        for (int e = 0; e < E_NUM; e++) {
#pragma unroll
            for (int off = 16; off > 0; off >>= 1)
                acc[e] += __shfl_xor_sync(0xFFFFFFFFu, acc[e], off);
        }
        if (lane == 0) {
            int e1 = 0; float l1 = acc[0];
#pragma unroll
            for (int e = 1; e < E_NUM; e++) if (acc[e] > l1) { l1 = acc[e]; e1 = e; }
            int e2 = -1; float l2 = -INFINITY;
#pragma unroll
            for (int e = 0; e < E_NUM; e++)
                if (e != e1 && acc[e] > l2) { l2 = acc[e]; e2 = e; }
            float p2  = expf(l2 - l1);
            float inv = 1.f / (1.f + p2);
            g_top2[t * 2] = e1; g_top2[t * 2 + 1] = e2;
            g_wts[t * 2] = inv; g_wts[t * 2 + 1] = p2 * inv;
        }
    }
}

// ----------------------------- scatter ----------------------------------------
__global__ __launch_bounds__(1024)
void scatter_kernel() {
    __shared__ int s_cnt[E_NUM];
    __shared__ int s_fill[E_NUM];
    int tid = threadIdx.x;
    if (tid < E_NUM) { s_cnt[tid] = 0; s_fill[tid] = 0; }
    __syncthreads();
    for (int t = tid; t < T_TOK; t += 1024) {
        atomicAdd(&s_cnt[g_top2[t * 2]], 1);
        atomicAdd(&s_cnt[g_top2[t * 2 + 1]], 1);
    }
    __syncthreads();
    if (tid == 0) {
        int s = 0;
        for (int e = 0; e < E_NUM; e++) { g_off[e] = s; s += s_cnt[e]; }
        g_off[E_NUM] = s;
    }
    __syncthreads();
    for (int t = tid; t < T_TOK; t += 1024) {
#pragma unroll
        for (int kk = 0; kk < TOPK; kk++) {
            int e = g_top2[t * 2 + kk];
            int p = atomicAdd(&s_fill[e], 1);
            int slot = g_off[e] + p;
            g_tok[slot]   = t;
            g_slotw[slot] = g_wts[t * 2 + kk];
            g_slot[t * 2 + kk] = slot;
        }
    }
}

// ----------------------------- GEMM1: 128 thr, 2x2 warps, 64x32 tiles --------
__global__ __launch_bounds__(128, 2)
void gemm1_mma() {
    extern __shared__ __half sm[];
    int e = blockIdx.z;
    int base = g_off[e], count = g_off[e + 1] - base;
    int m0 = blockIdx.y * BM;
    if (m0 >= count) return;
    int n0 = blockIdx.x * BN;

    int tid = threadIdx.x;
    int wid = tid >> 5, lane = tid & 31;
    int warpM = wid >> 1, warpN = wid & 1;   // 2x2 warp grid, 64x32 tiles
    int g = lane >> 2, tig = lane & 3;

    // loader: 16 rows/pass, 8 passes for A, 4 for each B
    int r  = tid >> 3;            // 0..15
    int hc = (tid & 7) * 8;

    const __half* Ap[8];
#pragma unroll
    for (int p = 0; p < 8; p++) {
        int mm = m0 + r + 16 * p; if (mm > count - 1) mm = count - 1;
        Ap[p] = g_xh + (size_t)g_tok[base + mm] * H_DIM + hc;
    }
    const __half* B1p = g_w1h + ((size_t)e * I_DIM + n0 + r) * H_DIM + hc;
    const __half* B2p = g_uph + ((size_t)e * I_DIM + n0 + r) * H_DIM + hc;

    uint32_t sb = smem_u32(sm);
    uint32_t dA[8], dB[4];
#pragma unroll
    for (int p = 0; p < 8; p++) dA[p] = ((r + 16 * p) * SROW2 + hc) * 2;
#pragma unroll
    for (int p = 0; p < 4; p++) dB[p] = ((r + 16 * p) * SROW2 + hc) * 2;

    // ldmatrix bases: A mt=0..3 (64 rows), B p=0..1 (32 cols)
    uint32_t lmA[4];
#pragma unroll
    for (int mt = 0; mt < 4; mt++) {
        int row = warpM * 64 + mt * 16 + (lane & 15);
        int kh  = (lane >> 4) * 8;
        lmA[mt] = (uint32_t)(row * SROW2 + kh) * 2u;
    }
    uint32_t lmB[2];
#pragma unroll
    for (int p = 0; p < 2; p++) {
        int nrow = warpN * 32 + p * 16 + ((lane >> 4) * 8) + (lane & 7);
        int kh   = ((lane >> 3) & 1) * 8;
        lmB[p] = (uint32_t)(nrow * SROW2 + kh) * 2u;
    }

    float accA[4][4][4], accU[4][4][4];
#pragma unroll
    for (int mt = 0; mt < 4; mt++)
#pragma unroll
        for (int nt = 0; nt < 4; nt++)
#pragma unroll
            for (int j = 0; j < 4; j++) { accA[mt][nt][j] = 0.f; accU[mt][nt][j] = 0.f; }

    const int KT = H_DIM / BK;   // 32

#define G1_LOAD(s, kt) do {                                                    \
        uint32_t stgb = sb + (uint32_t)(s) * STG1_B;                           \
        int ko = (kt) * BK;                                                    \
        cp16(stgb + dA[0], Ap[0] + ko);                                        \
        cp16(stgb + dA[1], Ap[1] + ko);                                        \
        cp16(stgb + dA[2], Ap[2] + ko);                                        \
        cp16(stgb + dA[3], Ap[3] + ko);                                        \
        cp16(stgb + dA[4], Ap[4] + ko);                                        \
        cp16(stgb + dA[5], Ap[5] + ko);                                        \
        cp16(stgb + dA[6], Ap[6] + ko);                                        \
        cp16(stgb + dA[7], Ap[7] + ko);                                        \
        cp16(stgb + A_BYTES + dB[0],           B1p + ko);                      \
        cp16(stgb + A_BYTES + dB[1],           B1p + 16 * H_DIM + ko);         \
        cp16(stgb + A_BYTES + dB[2],           B1p + 32 * H_DIM + ko);         \
        cp16(stgb + A_BYTES + dB[3],           B1p + 48 * H_DIM + ko);         \
        cp16(stgb + A_BYTES + B_BYTES + dB[0], B2p + ko);                      \
        cp16(stgb + A_BYTES + B_BYTES + dB[1], B2p + 16 * H_DIM + ko);         \
        cp16(stgb + A_BYTES + B_BYTES + dB[2], B2p + 32 * H_DIM + ko);         \
        cp16(stgb + A_BYTES + B_BYTES + dB[3], B2p + 48 * H_DIM + ko);         \
    } while (0)

    G1_LOAD(0, 0); CP_COMMIT();
    G1_LOAD(1, 1); CP_COMMIT();

    for (int kt = 0; kt < KT; kt++) {
        CP_WAIT(1);
        __syncthreads();
        if (kt + 2 < KT) G1_LOAD((kt + 2) % 3, kt + 2);
        CP_COMMIT();

        uint32_t stg = sb + (uint32_t)(kt % 3) * STG1_B;
        uint32_t sA  = stg;
        uint32_t sB1 = stg + A_BYTES;
        uint32_t sB2 = stg + A_BYTES + B_BYTES;

#pragma unroll
        for (int ks = 0; ks < 4; ks++) {
            uint32_t ko = ks * 32;        // 16 halves = 32 bytes
            uint32_t b1f[4][2], b2f[4][2];
#pragma unroll
            for (int p = 0; p < 2; p++) {
                uint32_t rb[4];
                LDSM_X4(rb, sB1 + lmB[p] + ko);
                b1f[2 * p][0] = rb[0]; b1f[2 * p][1] = rb[1];
                b1f[2 * p + 1][0] = rb[2]; b1f[2 * p + 1][1] = rb[3];
                LDSM_X4(rb, sB2 + lmB[p] + ko);
                b2f[2 * p][0] = rb[0]; b2f[2 * p][1] = rb[1];
                b2f[2 * p + 1][0] = rb[2]; b2f[2 * p + 1][1] = rb[3];
            }
#pragma unroll
            for (int mt = 0; mt < 4; mt++) {
                uint32_t a[4];
                LDSM_X4(a, sA + lmA[mt] + ko);
#pragma unroll
                for (int nt = 0; nt < 4; nt++) {
                    MMA_F16(accA[mt][nt], a, b1f[nt]);
                    MMA_F16(accU[mt][nt], a, b2f[nt]);
                }
            }
        }
    }
#undef G1_LOAD

#pragma unroll
    for (int mt = 0; mt < 4; mt++) {
        int row = m0 + warpM * 64 + mt * 16 + g;
        float w0 = (row < count)     ? g_slotw[base + row]     : 0.f;
        float w1 = (row + 8 < count) ? g_slotw[base + row + 8] : 0.f;
#pragma unroll
        for (int nt = 0; nt < 4; nt++) {
            int col = n0 + warpN * 32 + nt * 8 + 2 * tig;
            if (row < count) {
                __half2 v = __floats2half2_rn(
                    w0 * silu_mul(accA[mt][nt][0], accU[mt][nt][0]),
                    w0 * silu_mul(accA[mt][nt][1], accU[mt][nt][1]));
                *(__half2*)(g_h + (size_t)(base + row) * I_DIM + col) = v;
            }
            if (row + 8 < count) {
                __half2 v = __floats2half2_rn(
                    w1 * silu_mul(accA[mt][nt][2], accU[mt][nt][2]),
                    w1 * silu_mul(accA[mt][nt][3], accU[mt][nt][3]));
                *(__half2*)(g_h + (size_t)(base + row + 8) * I_DIM + col) = v;
            }
        }
    }
}

// ----------------------------- GEMM2: 128 thr, 2x2 warps, 64x32 tiles --------
__global__ __launch_bounds__(128, 2)
void gemm2_mma() {
    extern __shared__ __half sm[];
    int e = blockIdx.z;
    int base = g_off[e], count = g_off[e + 1] - base;
    int m0 = blockIdx.y * BM;
    if (m0 >= count) return;
    int n0 = blockIdx.x * BN;

    int tid = threadIdx.x;
    int wid = tid >> 5, lane = tid & 31;
    int warpM = wid >> 1, warpN = wid & 1;
    int g = lane >> 2, tig = lane & 3;

    int r  = tid >> 3;
    int hc = (tid & 7) * 8;

    const __half* Ap[8];
#pragma unroll
    for (int p = 0; p < 8; p++) {
        int mm = m0 + r + 16 * p; if (mm > count - 1) mm = count - 1;
        Ap[p] = g_h + (size_t)(base + mm) * I_DIM + hc;
    }
    const __half* Bp = g_w2h + ((size_t)e * H_DIM + n0 + r) * I_DIM + hc;

    uint32_t sb = smem_u32(sm);
    uint32_t dA[8], dB[4];
#pragma unroll
    for (int p = 0; p < 8; p++) dA[p] = ((r + 16 * p) * SROW2 + hc) * 2;
#pragma unroll
    for (int p = 0; p < 4; p++) dB[p] = ((r + 16 * p) * SROW2 + hc) * 2;

    uint32_t lmA[4];
#pragma unroll
    for (int mt = 0; mt < 4; mt++) {
        int row = warpM * 64 + mt * 16 + (lane & 15);
        int kh  = (lane >> 4) * 8;
        lmA[mt] = (uint32_t)(row * SROW2 + kh) * 2u;
    }
    uint32_t lmB[2];
#pragma unroll
    for (int p = 0; p < 2; p++) {
        int nrow = warpN * 32 + p * 16 + ((lane >> 4) * 8) + (lane & 7);
        int kh   = ((lane >> 3) & 1) * 8;
        lmB[p] = (uint32_t)(nrow * SROW2 + kh) * 2u;
    }

    float acc[4][4][4];
#pragma unroll
    for (int mt = 0; mt < 4; mt++)
#pragma unroll
        for (int nt = 0; nt < 4; nt++)
#pragma unroll
            for (int j = 0; j < 4; j++) acc[mt][nt][j] = 0.f;

    const int KT = I_DIM / BK;   // 22

#define G2_LOAD(s, kt) do {                                                    \
        uint32_t stgb = sb + (uint32_t)(s) * STG2_B;                           \
        int ko = (kt) * BK;                                                    \
        cp16(stgb + dA[0], Ap[0] + ko);                                        \
        cp16(stgb + dA[1], Ap[1] + ko);                                        \
        cp16(stgb + dA[2], Ap[2] + ko);                                        \
        cp16(stgb + dA[3], Ap[3] + ko);                                        \
        cp16(stgb + dA[4], Ap[4] + ko);                                        \
        cp16(stgb + dA[5], Ap[5] + ko);                                        \
        cp16(stgb + dA[6], Ap[6] + ko);                                        \
        cp16(stgb + dA[7], Ap[7] + ko);                                        \
        cp16(stgb + A_BYTES + dB[0], Bp + ko);                                 \
        cp16(stgb + A_BYTES + dB[1], Bp + 16 * I_DIM + ko);                    \
        cp16(stgb + A_BYTES + dB[2], Bp + 32 * I_DIM + ko);                    \
        cp16(stgb + A_BYTES + dB[3], Bp + 48 * I_DIM + ko);                    \
    } while (0)

    G2_LOAD(0, 0); CP_COMMIT();
    G2_LOAD(1, 1); CP_COMMIT();
    G2_LOAD(2, 2); CP_COMMIT();

    for (int kt = 0; kt < KT; kt++) {
        CP_WAIT(2);
        __syncthreads();
        if (kt + 3 < KT) G2_LOAD((kt + 3) & 3, kt + 3);
        CP_COMMIT();

        uint32_t stg = sb + (uint32_t)(kt & 3) * STG2_B;
        uint32_t sA  = stg;
        uint32_t sB  = stg + A_BYTES;

#pragma unroll
        for (int ks = 0; ks < 4; ks++) {
            uint32_t ko = ks * 32;
            uint32_t bf[4][2];
#pragma unroll
            for (int p = 0; p < 2; p++) {
                uint32_t rb[4];
                LDSM_X4(rb, sB + lmB[p] + ko);
                bf[2 * p][0] = rb[0]; bf[2 * p][1] = rb[1];
                bf[2 * p + 1][0] = rb[2]; bf[2 * p + 1][1] = rb[3];
            }
#pragma unroll
            for (int mt = 0; mt < 4; mt++) {
                uint32_t a[4];
                LDSM_X4(a, sA + lmA[mt] + ko);
#pragma unroll
                for (int nt = 0; nt < 4; nt++) MMA_F16(acc[mt][nt], a, bf[nt]);
            }
        }
    }
#undef G2_LOAD

#pragma unroll
    for (int mt = 0; mt < 4; mt++) {
#pragma unroll
        for (int nt = 0; nt < 4; nt++) {
            int row = m0 + warpM * 64 + mt * 16 + g;
            int col = n0 + warpN * 32 + nt * 8 + 2 * tig;
            if (row < count) {
                float2 v = make_float2(acc[mt][nt][0], acc[mt][nt][1]);
                *(float2*)(g_o2 + (size_t)(base + row) * H_DIM + col) = v;
            }
            if (row + 8 < count) {
                float2 v = make_float2(acc[mt][nt][2], acc[mt][nt][3]);
                *(float2*)(g_o2 + (size_t)(base + row + 8) * H_DIM + col) = v;
            }
        }
    }
}

// ----------------------------- combine ---------------------------------------
__global__ void combine_kernel(float4* __restrict__ out) {
    int idx = blockIdx.x * blockDim.x + threadIdx.x;
    int t = idx >> 9;
    int c = idx & 511;
    const float4* r0 = (const float4*)(g_o2 + (size_t)g_slot[t * 2]     * H_DIM) + c;
    const float4* r1 = (const float4*)(g_o2 + (size_t)g_slot[t * 2 + 1] * H_DIM) + c;
    float4 a = *r0, b = *r1, v;
    v.x = a.x + b.x;
    v.y = a.y + b.y;
    v.z = a.z + b.z;
    v.w = a.w + b.w;
    out[idx] = v;
}

// ----------------------------- launch -----------------------------------------
extern "C" void kernel_launch(void* const* d_in, const int* in_sizes, int n_in,
                              void* d_out, int out_size) {
    const float* x  = (const float*)d_in[0];
    const float* gw = (const float*)d_in[1];
    const float* W1 = (const float*)d_in[2];
    const float* Up = (const float*)d_in[3];
    const float* W2 = (const float*)d_in[4];
    float* out = (float*)d_out;

    const int SMEMG = E_NUM * H_DIM * 4;
    const int SMEM1 = 3 * STG1_B;    // 110,592
    const int SMEM2 = 4 * STG2_B;    // 110,592
    cudaFuncSetAttribute(gate_kernel, cudaFuncAttributeMaxDynamicSharedMemorySize, SMEMG);
    cudaFuncSetAttribute(gemm1_mma,  cudaFuncAttributeMaxDynamicSharedMemorySize, SMEM1);
    cudaFuncSetAttribute(gemm2_mma,  cudaFuncAttributeMaxDynamicSharedMemorySize, SMEM2);

    f2h_all<<<8192, 256>>>((const float4*)W1, (const float4*)Up, (const float4*)W2); // 0
    gate_kernel<<<T_TOK / 32, 256, SMEMG>>>(x, gw);                                  // 1
    scatter_kernel<<<1, 1024>>>();                                                   // 2

    dim3 g1(I_DIM / BN, T_TOK / BM, E_NUM);          // 3: (22, 64, 16)
    gemm1_mma<<<g1, 128, SMEM1>>>();

    dim3 g2(H_DIM / BN, T_TOK / BM, E_NUM);          // 4: (32, 64, 16)
    gemm2_mma<<<g2, 128, SMEM2>>>();

    combine_kernel<<<(T_TOK * H_DIM / 4) / 256, 256>>>((float4*)out);                // 5
}

// round 9
// speedup vs baseline: 1.1194x; 1.1194x over previous
#include <cuda_runtime.h>
#include <cuda_fp16.h>
#include <math.h>
#include <stdint.h>

#define T_TOK 8192
#define H_DIM 2048
#define I_DIM 1408
#define E_NUM 16
#define TOPK  2
#define NSLOT (T_TOK * TOPK)

#define BM 128
#define BN 64
#define BK 64                 // halves per K-slab (128 B/row)
#define SROW2 72              // padded halves per smem row (144 B)
#define A_BYTES (128 * SROW2 * 2)       // 18432 (128 rows)
#define B_BYTES (64  * SROW2 * 2)       // 9216  (64 rows)
#define STG1_B (A_BYTES + 2 * B_BYTES)  // 36864 (gemm1: A + B1 + B2)
#define STG2_B (2 * A_BYTES)            // 36864 (gemm2: A128 + B128)

// ----------------------------- device scratch --------------------------------
__device__ __half g_xh [(size_t)T_TOK * H_DIM];
__device__ __half g_w1h[(size_t)E_NUM * I_DIM * H_DIM];
__device__ __half g_uph[(size_t)E_NUM * I_DIM * H_DIM];
__device__ __half g_w2h[(size_t)E_NUM * H_DIM * I_DIM];
__device__ __half g_h  [(size_t)NSLOT * I_DIM];
__device__ float  g_o2 [(size_t)NSLOT * H_DIM];
__device__ int    g_top2[T_TOK * 2];
__device__ float  g_wts [T_TOK * 2];
__device__ int    g_off [E_NUM + 1];
__device__ int    g_tok [NSLOT];
__device__ float  g_slotw[NSLOT];
__device__ int    g_slot[T_TOK * 2];

// ----------------------------- helpers ---------------------------------------
__device__ __forceinline__ uint32_t smem_u32(const void* p) {
    uint32_t a;
    asm("{ .reg .u64 t; cvta.to.shared.u64 t, %1; cvt.u32.u64 %0, t; }" : "=r"(a) : "l"(p));
    return a;
}
__device__ __forceinline__ void cp16(uint32_t dst, const void* src) {
    asm volatile("cp.async.cg.shared.global [%0], [%1], 16;"
                 :: "r"(dst), "l"(__cvta_generic_to_global(src)) : "memory");
}
#define CP_COMMIT() asm volatile("cp.async.commit_group;" ::: "memory")
#define CP_WAIT(n)  asm volatile("cp.async.wait_group %0;" :: "n"(n) : "memory")

#define MMA_F16(d, a, b)                                                       \
    asm volatile("mma.sync.aligned.m16n8k16.row.col.f32.f16.f16.f32 "          \
        "{%0,%1,%2,%3}, {%4,%5,%6,%7}, {%8,%9}, {%0,%1,%2,%3};"                \
        : "+f"((d)[0]), "+f"((d)[1]), "+f"((d)[2]), "+f"((d)[3])               \
        : "r"((a)[0]), "r"((a)[1]), "r"((a)[2]), "r"((a)[3]),                  \
          "r"((b)[0]), "r"((b)[1]))

#define LDSM_X4(r, addr)                                                       \
    asm volatile("ldmatrix.sync.aligned.m8n8.x4.shared.b16 {%0,%1,%2,%3}, [%4];" \
        : "=r"((r)[0]), "=r"((r)[1]), "=r"((r)[2]), "=r"((r)[3]) : "r"(addr))

__device__ __forceinline__ float silu_mul(float a, float u) {
    return (a / (1.f + __expf(-a))) * u;
}

// ----------------------------- fp16 weight conversion ------------------------
__global__ void f2h_all(const float4* __restrict__ w1, const float4* __restrict__ up,
                        const float4* __restrict__ w2) {
    const long n4 = (long)E_NUM * I_DIM * H_DIM / 4;
    long i = blockIdx.x * (long)blockDim.x + threadIdx.x;
    long stride = (long)gridDim.x * blockDim.x;
    for (; i < 3 * n4; i += stride) {
        const float4* src;
        __half* dsth;
        long j;
        if (i < n4)          { src = w1 + i;            dsth = g_w1h; j = i; }
        else if (i < 2 * n4) { src = up + (i - n4);     dsth = g_uph; j = i - n4; }
        else                 { src = w2 + (i - 2 * n4); dsth = g_w2h; j = i - 2 * n4; }
        float4 v = *src;
        __half2 h01 = __floats2half2_rn(v.x, v.y);
        __half2 h23 = __floats2half2_rn(v.z, v.w);
        uint2 u;
        u.x = *(uint32_t*)&h01;
        u.y = *(uint32_t*)&h23;
        *(uint2*)(dsth + j * 4) = u;
    }
}

// ----------------------------- gate (+ x -> fp16) ----------------------------
__global__ __launch_bounds__(256)
void gate_kernel(const float* __restrict__ x, const float* __restrict__ gw) {
    extern __shared__ float sgw[];
    int tid = threadIdx.x;
    for (int i = tid; i < E_NUM * H_DIM / 4; i += 256)
        ((float4*)sgw)[i] = ((const float4*)gw)[i];
    __syncthreads();

    int warp = tid >> 5, lane = tid & 31;
#pragma unroll
    for (int i = 0; i < 4; i++) {
        int t = blockIdx.x * 32 + warp * 4 + i;
        const float* xr = x + (size_t)t * H_DIM;
        float acc[E_NUM];
#pragma unroll
        for (int e = 0; e < E_NUM; e++) acc[e] = 0.f;
        for (int k = lane * 2; k < H_DIM; k += 64) {
            float2 xv = *(const float2*)(xr + k);
            __half2 hv = __floats2half2_rn(xv.x, xv.y);
            *(__half2*)(g_xh + (size_t)t * H_DIM + k) = hv;
#pragma unroll
            for (int e = 0; e < E_NUM; e++) {
                float2 g = *(const float2*)(sgw + e * H_DIM + k);
                acc[e] += xv.x * g.x + xv.y * g.y;
            }
        }
#pragma unroll
        for (int e = 0; e < E_NUM; e++) {
#pragma unroll
            for (int off = 16; off > 0; off >>= 1)
                acc[e] += __shfl_xor_sync(0xFFFFFFFFu, acc[e], off);
        }
        if (lane == 0) {
            int e1 = 0; float l1 = acc[0];
#pragma unroll
            for (int e = 1; e < E_NUM; e++) if (acc[e] > l1) { l1 = acc[e]; e1 = e; }
            int e2 = -1; float l2 = -INFINITY;
#pragma unroll
            for (int e = 0; e < E_NUM; e++)
                if (e != e1 && acc[e] > l2) { l2 = acc[e]; e2 = e; }
            float p2  = expf(l2 - l1);
            float inv = 1.f / (1.f + p2);
            g_top2[t * 2] = e1; g_top2[t * 2 + 1] = e2;
            g_wts[t * 2] = inv; g_wts[t * 2 + 1] = p2 * inv;
        }
    }
}

// ----------------------------- scatter ----------------------------------------
__global__ __launch_bounds__(1024)
void scatter_kernel() {
    __shared__ int s_cnt[E_NUM];
    __shared__ int s_fill[E_NUM];
    int tid = threadIdx.x;
    if (tid < E_NUM) { s_cnt[tid] = 0; s_fill[tid] = 0; }
    __syncthreads();
    for (int t = tid; t < T_TOK; t += 1024) {
        atomicAdd(&s_cnt[g_top2[t * 2]], 1);
        atomicAdd(&s_cnt[g_top2[t * 2 + 1]], 1);
    }
    __syncthreads();
    if (tid == 0) {
        int s = 0;
        for (int e = 0; e < E_NUM; e++) { g_off[e] = s; s += s_cnt[e]; }
        g_off[E_NUM] = s;
    }
    __syncthreads();
    for (int t = tid; t < T_TOK; t += 1024) {
#pragma unroll
        for (int kk = 0; kk < TOPK; kk++) {
            int e = g_top2[t * 2 + kk];
            int p = atomicAdd(&s_fill[e], 1);
            int slot = g_off[e] + p;
            g_tok[slot]   = t;
            g_slotw[slot] = g_wts[t * 2 + kk];
            g_slot[t * 2 + kk] = slot;
        }
    }
}

// ----------------------------- GEMM1 (R7 config: 256 thr, 4x2, 32x32 dual) ---
__global__ __launch_bounds__(256, 2)
void gemm1_mma() {
    extern __shared__ __half sm[];
    int e = blockIdx.z;
    int base = g_off[e], count = g_off[e + 1] - base;
    int m0 = blockIdx.y * BM;
    if (m0 >= count) return;
    int n0 = blockIdx.x * BN;

    int tid = threadIdx.x;
    int wid = tid >> 5, lane = tid & 31;
    int warpM = wid >> 1, warpN = wid & 1;
    int g = lane >> 2, tig = lane & 3;

    int r  = tid >> 3;            // 0..31
    int hc = (tid & 7) * 8;

    const __half* Ap[4];
#pragma unroll
    for (int p = 0; p < 4; p++) {
        int mm = m0 + r + 32 * p; if (mm > count - 1) mm = count - 1;
        Ap[p] = g_xh + (size_t)g_tok[base + mm] * H_DIM + hc;
    }
    const __half* B1p[2];
    const __half* B2p[2];
#pragma unroll
    for (int p = 0; p < 2; p++) {
        int nn = n0 + r + 32 * p;
        B1p[p] = g_w1h + ((size_t)e * I_DIM + nn) * H_DIM + hc;
        B2p[p] = g_uph + ((size_t)e * I_DIM + nn) * H_DIM + hc;
    }

    uint32_t sb = smem_u32(sm);
    uint32_t dA[4], dB[2];
#pragma unroll
    for (int p = 0; p < 4; p++) dA[p] = ((r + 32 * p) * SROW2 + hc) * 2;
#pragma unroll
    for (int p = 0; p < 2; p++) dB[p] = ((r + 32 * p) * SROW2 + hc) * 2;

    uint32_t lmA[2];
#pragma unroll
    for (int mt = 0; mt < 2; mt++) {
        int row = warpM * 32 + mt * 16 + (lane & 15);
        int kh  = (lane >> 4) * 8;
        lmA[mt] = (uint32_t)(row * SROW2 + kh) * 2u;
    }
    uint32_t lmB[2];
#pragma unroll
    for (int p = 0; p < 2; p++) {
        int nrow = warpN * 32 + p * 16 + ((lane >> 4) * 8) + (lane & 7);
        int kh   = ((lane >> 3) & 1) * 8;
        lmB[p] = (uint32_t)(nrow * SROW2 + kh) * 2u;
    }

    float accA[2][4][4], accU[2][4][4];
#pragma unroll
    for (int mt = 0; mt < 2; mt++)
#pragma unroll
        for (int nt = 0; nt < 4; nt++)
#pragma unroll
            for (int j = 0; j < 4; j++) { accA[mt][nt][j] = 0.f; accU[mt][nt][j] = 0.f; }

    const int KT = H_DIM / BK;   // 32

#define G1_LOAD(s, kt) do {                                                    \
        uint32_t stgb = sb + (uint32_t)(s) * STG1_B;                           \
        int ko = (kt) * BK;                                                    \
        cp16(stgb + dA[0],                     Ap[0]  + ko);                   \
        cp16(stgb + dA[1],                     Ap[1]  + ko);                   \
        cp16(stgb + dA[2],                     Ap[2]  + ko);                   \
        cp16(stgb + dA[3],                     Ap[3]  + ko);                   \
        cp16(stgb + A_BYTES + dB[0],           B1p[0] + ko);                   \
        cp16(stgb + A_BYTES + dB[1],           B1p[1] + ko);                   \
        cp16(stgb + A_BYTES + B_BYTES + dB[0], B2p[0] + ko);                   \
        cp16(stgb + A_BYTES + B_BYTES + dB[1], B2p[1] + ko);                   \
    } while (0)

    G1_LOAD(0, 0); CP_COMMIT();
    G1_LOAD(1, 1); CP_COMMIT();

    for (int kt = 0; kt < KT; kt++) {
        CP_WAIT(1);
        __syncthreads();
        if (kt + 2 < KT) G1_LOAD((kt + 2) % 3, kt + 2);
        CP_COMMIT();

        uint32_t stg = sb + (uint32_t)(kt % 3) * STG1_B;
        uint32_t sA  = stg;
        uint32_t sB1 = stg + A_BYTES;
        uint32_t sB2 = stg + A_BYTES + B_BYTES;

#pragma unroll
        for (int ks = 0; ks < 4; ks++) {
            uint32_t ko = ks * 32;        // 16 halves = 32 bytes
            uint32_t a[2][4];
            LDSM_X4(a[0], sA + lmA[0] + ko);
            LDSM_X4(a[1], sA + lmA[1] + ko);
            uint32_t b1f[4][2], b2f[4][2];
#pragma unroll
            for (int p = 0; p < 2; p++) {
                uint32_t rb[4];
                LDSM_X4(rb, sB1 + lmB[p] + ko);
                b1f[2 * p][0] = rb[0]; b1f[2 * p][1] = rb[1];
                b1f[2 * p + 1][0] = rb[2]; b1f[2 * p + 1][1] = rb[3];
                LDSM_X4(rb, sB2 + lmB[p] + ko);
                b2f[2 * p][0] = rb[0]; b2f[2 * p][1] = rb[1];
                b2f[2 * p + 1][0] = rb[2]; b2f[2 * p + 1][1] = rb[3];
            }
#pragma unroll
            for (int nt = 0; nt < 4; nt++) {
#pragma unroll
                for (int mt = 0; mt < 2; mt++) {
                    MMA_F16(accA[mt][nt], a[mt], b1f[nt]);
                    MMA_F16(accU[mt][nt], a[mt], b2f[nt]);
                }
            }
        }
    }
#undef G1_LOAD

#pragma unroll
    for (int mt = 0; mt < 2; mt++) {
        int row = m0 + warpM * 32 + mt * 16 + g;
        float w0 = (row < count)     ? g_slotw[base + row]     : 0.f;
        float w1 = (row + 8 < count) ? g_slotw[base + row + 8] : 0.f;
#pragma unroll
        for (int nt = 0; nt < 4; nt++) {
            int col = n0 + warpN * 32 + nt * 8 + 2 * tig;
            if (row < count) {
                __half2 v = __floats2half2_rn(
                    w0 * silu_mul(accA[mt][nt][0], accU[mt][nt][0]),
                    w0 * silu_mul(accA[mt][nt][1], accU[mt][nt][1]));
                *(__half2*)(g_h + (size_t)(base + row) * I_DIM + col) = v;
            }
            if (row + 8 < count) {
                __half2 v = __floats2half2_rn(
                    w1 * silu_mul(accA[mt][nt][2], accU[mt][nt][2]),
                    w1 * silu_mul(accA[mt][nt][3], accU[mt][nt][3]));
                *(__half2*)(g_h + (size_t)(base + row + 8) * I_DIM + col) = v;
            }
        }
    }
}

// ----------------------------- GEMM2: 128x128 CTA, 256 thr, 2x4, 64x32 -------
__global__ __launch_bounds__(256, 2)
void gemm2_mma() {
    extern __shared__ __half sm[];
    int e = blockIdx.z;
    int base = g_off[e], count = g_off[e + 1] - base;
    int m0 = blockIdx.y * BM;
    if (m0 >= count) return;
    int n0 = blockIdx.x * 128;   // BN2 = 128

    int tid = threadIdx.x;
    int wid = tid >> 5, lane = tid & 31;
    int warpM = wid >> 2, warpN = wid & 3;   // 2x4 grid, 64x32 warp tiles
    int g = lane >> 2, tig = lane & 3;

    int r  = tid >> 3;            // 0..31
    int hc = (tid & 7) * 8;

    const __half* Ap[4];
#pragma unroll
    for (int p = 0; p < 4; p++) {
        int mm = m0 + r + 32 * p; if (mm > count - 1) mm = count - 1;
        Ap[p] = g_h + (size_t)(base + mm) * I_DIM + hc;
    }
    const __half* Bp = g_w2h + ((size_t)e * H_DIM + n0 + r) * I_DIM + hc;

    uint32_t sb = smem_u32(sm);
    uint32_t dA[4];
#pragma unroll
    for (int p = 0; p < 4; p++) dA[p] = ((r + 32 * p) * SROW2 + hc) * 2;

    uint32_t lmA[4];
#pragma unroll
    for (int mt = 0; mt < 4; mt++) {
        int row = warpM * 64 + mt * 16 + (lane & 15);
        int kh  = (lane >> 4) * 8;
        lmA[mt] = (uint32_t)(row * SROW2 + kh) * 2u;
    }
    uint32_t lmB[2];
#pragma unroll
    for (int p = 0; p < 2; p++) {
        int nrow = warpN * 32 + p * 16 + ((lane >> 4) * 8) + (lane & 7);
        int kh   = ((lane >> 3) & 1) * 8;
        lmB[p] = (uint32_t)(nrow * SROW2 + kh) * 2u;
    }

    float acc[4][4][4];
#pragma unroll
    for (int mt = 0; mt < 4; mt++)
#pragma unroll
        for (int nt = 0; nt < 4; nt++)
#pragma unroll
            for (int j = 0; j < 4; j++) acc[mt][nt][j] = 0.f;

    const int KT = I_DIM / BK;   // 22

#define G2_LOAD(s, kt) do {                                                    \
        uint32_t stgb = sb + (uint32_t)(s) * STG2_B;                           \
        int ko = (kt) * BK;                                                    \
        cp16(stgb + dA[0], Ap[0] + ko);                                        \
        cp16(stgb + dA[1], Ap[1] + ko);                                        \
        cp16(stgb + dA[2], Ap[2] + ko);                                        \
        cp16(stgb + dA[3], Ap[3] + ko);                                        \
        cp16(stgb + A_BYTES + dA[0], Bp + ko);                                 \
        cp16(stgb + A_BYTES + dA[1], Bp + 32 * I_DIM + ko);                    \
        cp16(stgb + A_BYTES + dA[2], Bp + 64 * I_DIM + ko);                    \
        cp16(stgb + A_BYTES + dA[3], Bp + 96 * I_DIM + ko);                    \
    } while (0)

    G2_LOAD(0, 0); CP_COMMIT();
    G2_LOAD(1, 1); CP_COMMIT();

    for (int kt = 0; kt < KT; kt++) {
        CP_WAIT(1);
        __syncthreads();
        if (kt + 2 < KT) G2_LOAD((kt + 2) % 3, kt + 2);
        CP_COMMIT();

        uint32_t stg = sb + (uint32_t)(kt % 3) * STG2_B;
        uint32_t sA  = stg;
        uint32_t sB  = stg + A_BYTES;

#pragma unroll
        for (int ks = 0; ks < 4; ks++) {
            uint32_t ko = ks * 32;
            uint32_t bf[4][2];
#pragma unroll
            for (int p = 0; p < 2; p++) {
                uint32_t rb[4];
                LDSM_X4(rb, sB + lmB[p] + ko);
                bf[2 * p][0] = rb[0]; bf[2 * p][1] = rb[1];
                bf[2 * p + 1][0] = rb[2]; bf[2 * p + 1][1] = rb[3];
            }
#pragma unroll
            for (int mt = 0; mt < 4; mt++) {
                uint32_t a[4];
                LDSM_X4(a, sA + lmA[mt] + ko);
#pragma unroll
                for (int nt = 0; nt < 4; nt++) MMA_F16(acc[mt][nt], a, bf[nt]);
            }
        }
    }
#undef G2_LOAD

#pragma unroll
    for (int mt = 0; mt < 4; mt++) {
#pragma unroll
        for (int nt = 0; nt < 4; nt++) {
            int row = m0 + warpM * 64 + mt * 16 + g;
            int col = n0 + warpN * 32 + nt * 8 + 2 * tig;
            if (row < count) {
                float2 v = make_float2(acc[mt][nt][0], acc[mt][nt][1]);
                *(float2*)(g_o2 + (size_t)(base + row) * H_DIM + col) = v;
            }
            if (row + 8 < count) {
                float2 v = make_float2(acc[mt][nt][2], acc[mt][nt][3]);
                *(float2*)(g_o2 + (size_t)(base + row + 8) * H_DIM + col) = v;
            }
        }
    }
}

// ----------------------------- combine ---------------------------------------
__global__ void combine_kernel(float4* __restrict__ out) {
    int idx = blockIdx.x * blockDim.x + threadIdx.x;
    int t = idx >> 9;
    int c = idx & 511;
    const float4* r0 = (const float4*)(g_o2 + (size_t)g_slot[t * 2]     * H_DIM) + c;
    const float4* r1 = (const float4*)(g_o2 + (size_t)g_slot[t * 2 + 1] * H_DIM) + c;
    float4 a = *r0, b = *r1, v;
    v.x = a.x + b.x;
    v.y = a.y + b.y;
    v.z = a.z + b.z;
    v.w = a.w + b.w;
    out[idx] = v;
}

// ----------------------------- launch -----------------------------------------
extern "C" void kernel_launch(void* const* d_in, const int* in_sizes, int n_in,
                              void* d_out, int out_size) {
    const float* x  = (const float*)d_in[0];
    const float* gw = (const float*)d_in[1];
    const float* W1 = (const float*)d_in[2];
    const float* Up = (const float*)d_in[3];
    const float* W2 = (const float*)d_in[4];
    float* out = (float*)d_out;

    const int SMEMG = E_NUM * H_DIM * 4;
    const int SMEM1 = 3 * STG1_B;    // 110,592
    const int SMEM2 = 3 * STG2_B;    // 110,592
    cudaFuncSetAttribute(gate_kernel, cudaFuncAttributeMaxDynamicSharedMemorySize, SMEMG);
    cudaFuncSetAttribute(gemm1_mma,  cudaFuncAttributeMaxDynamicSharedMemorySize, SMEM1);
    cudaFuncSetAttribute(gemm2_mma,  cudaFuncAttributeMaxDynamicSharedMemorySize, SMEM2);

    f2h_all<<<8192, 256>>>((const float4*)W1, (const float4*)Up, (const float4*)W2); // 0
    gate_kernel<<<T_TOK / 32, 256, SMEMG>>>(x, gw);                                  // 1
    scatter_kernel<<<1, 1024>>>();                                                   // 2

    dim3 g1(I_DIM / BN, T_TOK / BM, E_NUM);          // 3: (22, 64, 16)
    gemm1_mma<<<g1, 256, SMEM1>>>();

    dim3 g2(H_DIM / 128, T_TOK / BM, E_NUM);         // 4: (16, 64, 16)
    gemm2_mma<<<g2, 256, SMEM2>>>();

    combine_kernel<<<(T_TOK * H_DIM / 4) / 256, 256>>>((float4*)out);                // 5
}

// round 10
// speedup vs baseline: 1.1374x; 1.0161x over previous
#include <cuda_runtime.h>
#include <cuda_fp16.h>
#include <math.h>
#include <stdint.h>

#define T_TOK 8192
#define H_DIM 2048
#define I_DIM 1408
#define E_NUM 16
#define TOPK  2
#define NSLOT (T_TOK * TOPK)

#define BM 128
#define BN 64
#define BK 64                 // halves per K-slab (128 B/row)
#define SROW2 72              // padded halves per smem row (144 B)
#define A_BYTES (128 * SROW2 * 2)       // 18432 (128 rows)
#define B_BYTES (64  * SROW2 * 2)       // 9216  (64 rows)
#define STG1_B (A_BYTES + 2 * B_BYTES)  // 36864 (gemm1: A + B1 + B2)
#define STG2_B (2 * A_BYTES)            // 36864 (gemm2: A128 + B128)

#define GATE_BLKS 256
#define PREP_BLKS (GATE_BLKS + 8192)

// ----------------------------- device scratch --------------------------------
__device__ __half g_xh [(size_t)T_TOK * H_DIM];
__device__ __half g_w1h[(size_t)E_NUM * I_DIM * H_DIM];
__device__ __half g_uph[(size_t)E_NUM * I_DIM * H_DIM];
__device__ __half g_w2h[(size_t)E_NUM * H_DIM * I_DIM];
__device__ __half g_h  [(size_t)NSLOT * I_DIM];
__device__ float  g_o2 [(size_t)NSLOT * H_DIM];
__device__ int    g_top2[T_TOK * 2];
__device__ float  g_wts [T_TOK * 2];
__device__ int    g_off [E_NUM + 1];
__device__ int    g_tok [NSLOT];
__device__ float  g_slotw[NSLOT];
__device__ int    g_slot[T_TOK * 2];

// ----------------------------- helpers ---------------------------------------
__device__ __forceinline__ uint32_t smem_u32(const void* p) {
    uint32_t a;
    asm("{ .reg .u64 t; cvta.to.shared.u64 t, %1; cvt.u32.u64 %0, t; }" : "=r"(a) : "l"(p));
    return a;
}
__device__ __forceinline__ void cp16(uint32_t dst, const void* src) {
    asm volatile("cp.async.cg.shared.global [%0], [%1], 16;"
                 :: "r"(dst), "l"(__cvta_generic_to_global(src)) : "memory");
}
#define CP_COMMIT() asm volatile("cp.async.commit_group;" ::: "memory")
#define CP_WAIT(n)  asm volatile("cp.async.wait_group %0;" :: "n"(n) : "memory")

#define MMA_F16(d, a, b)                                                       \
    asm volatile("mma.sync.aligned.m16n8k16.row.col.f32.f16.f16.f32 "          \
        "{%0,%1,%2,%3}, {%4,%5,%6,%7}, {%8,%9}, {%0,%1,%2,%3};"                \
        : "+f"((d)[0]), "+f"((d)[1]), "+f"((d)[2]), "+f"((d)[3])               \
        : "r"((a)[0]), "r"((a)[1]), "r"((a)[2]), "r"((a)[3]),                  \
          "r"((b)[0]), "r"((b)[1]))

#define LDSM_X4(r, addr)                                                       \
    asm volatile("ldmatrix.sync.aligned.m8n8.x4.shared.b16 {%0,%1,%2,%3}, [%4];" \
        : "=r"((r)[0]), "=r"((r)[1]), "=r"((r)[2]), "=r"((r)[3]) : "r"(addr))

__device__ __forceinline__ float silu_mul(float a, float u) {
    return (a / (1.f + __expf(-a))) * u;
}

// ----------------------------- fused prep: gate + x->fp16 + weights->fp16 ----
__global__ __launch_bounds__(256)
void prep_kernel(const float* __restrict__ x,  const float* __restrict__ gw,
                 const float4* __restrict__ w1, const float4* __restrict__ up,
                 const float4* __restrict__ w2) {
    int tid = threadIdx.x;
    if (blockIdx.x < GATE_BLKS) {
        // ---- gate part: 32 tokens per block, gw read via L2 (128 KB, resident)
        int warp = tid >> 5, lane = tid & 31;
#pragma unroll
        for (int i = 0; i < 4; i++) {
            int t = blockIdx.x * 32 + warp * 4 + i;
            const float* xr = x + (size_t)t * H_DIM;
            float acc[E_NUM];
#pragma unroll
            for (int e = 0; e < E_NUM; e++) acc[e] = 0.f;
            for (int k = lane * 2; k < H_DIM; k += 64) {
                float2 xv = *(const float2*)(xr + k);
                __half2 hv = __floats2half2_rn(xv.x, xv.y);
                *(__half2*)(g_xh + (size_t)t * H_DIM + k) = hv;
#pragma unroll
                for (int e = 0; e < E_NUM; e++) {
                    float2 g = __ldg((const float2*)(gw + e * H_DIM + k));
                    acc[e] += xv.x * g.x + xv.y * g.y;
                }
            }
#pragma unroll
            for (int e = 0; e < E_NUM; e++) {
#pragma unroll
                for (int off = 16; off > 0; off >>= 1)
                    acc[e] += __shfl_xor_sync(0xFFFFFFFFu, acc[e], off);
            }
            if (lane == 0) {
                int e1 = 0; float l1 = acc[0];
#pragma unroll
                for (int e = 1; e < E_NUM; e++) if (acc[e] > l1) { l1 = acc[e]; e1 = e; }
                int e2 = -1; float l2 = -INFINITY;
#pragma unroll
                for (int e = 0; e < E_NUM; e++)
                    if (e != e1 && acc[e] > l2) { l2 = acc[e]; e2 = e; }
                float p2  = expf(l2 - l1);
                float inv = 1.f / (1.f + p2);
                g_top2[t * 2] = e1; g_top2[t * 2 + 1] = e2;
                g_wts[t * 2] = inv; g_wts[t * 2 + 1] = p2 * inv;
            }
        }
    } else {
        // ---- f2h part: grid-stride fp32 -> fp16 over W1, Up, W2
        const long n4 = (long)E_NUM * I_DIM * H_DIM / 4;
        long i = (long)(blockIdx.x - GATE_BLKS) * 256 + tid;
        long stride = (long)(PREP_BLKS - GATE_BLKS) * 256;
        for (; i < 3 * n4; i += stride) {
            const float4* src;
            __half* dsth;
            long j;
            if (i < n4)          { src = w1 + i;            dsth = g_w1h; j = i; }
            else if (i < 2 * n4) { src = up + (i - n4);     dsth = g_uph; j = i - n4; }
            else                 { src = w2 + (i - 2 * n4); dsth = g_w2h; j = i - 2 * n4; }
            float4 v = *src;
            __half2 h01 = __floats2half2_rn(v.x, v.y);
            __half2 h23 = __floats2half2_rn(v.z, v.w);
            uint2 u;
            u.x = *(uint32_t*)&h01;
            u.y = *(uint32_t*)&h23;
            *(uint2*)(dsth + j * 4) = u;
        }
    }
}

// ----------------------------- scatter ----------------------------------------
__global__ __launch_bounds__(1024)
void scatter_kernel() {
    __shared__ int s_cnt[E_NUM];
    __shared__ int s_fill[E_NUM];
    int tid = threadIdx.x;
    if (tid < E_NUM) { s_cnt[tid] = 0; s_fill[tid] = 0; }
    __syncthreads();
    for (int t = tid; t < T_TOK; t += 1024) {
        atomicAdd(&s_cnt[g_top2[t * 2]], 1);
        atomicAdd(&s_cnt[g_top2[t * 2 + 1]], 1);
    }
    __syncthreads();
    if (tid == 0) {
        int s = 0;
        for (int e = 0; e < E_NUM; e++) { g_off[e] = s; s += s_cnt[e]; }
        g_off[E_NUM] = s;
    }
    __syncthreads();
    for (int t = tid; t < T_TOK; t += 1024) {
#pragma unroll
        for (int kk = 0; kk < TOPK; kk++) {
            int e = g_top2[t * 2 + kk];
            int p = atomicAdd(&s_fill[e], 1);
            int slot = g_off[e] + p;
            g_tok[slot]   = t;
            g_slotw[slot] = g_wts[t * 2 + kk];
            g_slot[t * 2 + kk] = slot;
        }
    }
}

// ----------------------------- GEMM1 (256 thr, 4x2 warps, 32x32 dual) --------
__global__ __launch_bounds__(256, 2)
void gemm1_mma() {
    extern __shared__ __half sm[];
    int e = blockIdx.z;
    int base = g_off[e], count = g_off[e + 1] - base;
    int m0 = blockIdx.y * BM;
    if (m0 >= count) return;
    int n0 = blockIdx.x * BN;

    int tid = threadIdx.x;
    int wid = tid >> 5, lane = tid & 31;
    int warpM = wid >> 1, warpN = wid & 1;
    int g = lane >> 2, tig = lane & 3;

    int r  = tid >> 3;            // 0..31
    int hc = (tid & 7) * 8;

    const __half* Ap[4];
#pragma unroll
    for (int p = 0; p < 4; p++) {
        int mm = m0 + r + 32 * p; if (mm > count - 1) mm = count - 1;
        Ap[p] = g_xh + (size_t)g_tok[base + mm] * H_DIM + hc;
    }
    const __half* B1p[2];
    const __half* B2p[2];
#pragma unroll
    for (int p = 0; p < 2; p++) {
        int nn = n0 + r + 32 * p;
        B1p[p] = g_w1h + ((size_t)e * I_DIM + nn) * H_DIM + hc;
        B2p[p] = g_uph + ((size_t)e * I_DIM + nn) * H_DIM + hc;
    }

    uint32_t sb = smem_u32(sm);
    uint32_t dA[4], dB[2];
#pragma unroll
    for (int p = 0; p < 4; p++) dA[p] = ((r + 32 * p) * SROW2 + hc) * 2;
#pragma unroll
    for (int p = 0; p < 2; p++) dB[p] = ((r + 32 * p) * SROW2 + hc) * 2;

    uint32_t lmA[2];
#pragma unroll
    for (int mt = 0; mt < 2; mt++) {
        int row = warpM * 32 + mt * 16 + (lane & 15);
        int kh  = (lane >> 4) * 8;
        lmA[mt] = (uint32_t)(row * SROW2 + kh) * 2u;
    }
    uint32_t lmB[2];
#pragma unroll
    for (int p = 0; p < 2; p++) {
        int nrow = warpN * 32 + p * 16 + ((lane >> 4) * 8) + (lane & 7);
        int kh   = ((lane >> 3) & 1) * 8;
        lmB[p] = (uint32_t)(nrow * SROW2 + kh) * 2u;
    }

    float accA[2][4][4], accU[2][4][4];
#pragma unroll
    for (int mt = 0; mt < 2; mt++)
#pragma unroll
        for (int nt = 0; nt < 4; nt++)
#pragma unroll
            for (int j = 0; j < 4; j++) { accA[mt][nt][j] = 0.f; accU[mt][nt][j] = 0.f; }

    const int KT = H_DIM / BK;   // 32

#define G1_LOAD(s, kt) do {                                                    \
        uint32_t stgb = sb + (uint32_t)(s) * STG1_B;                           \
        int ko = (kt) * BK;                                                    \
        cp16(stgb + dA[0],                     Ap[0]  + ko);                   \
        cp16(stgb + dA[1],                     Ap[1]  + ko);                   \
        cp16(stgb + dA[2],                     Ap[2]  + ko);                   \
        cp16(stgb + dA[3],                     Ap[3]  + ko);                   \
        cp16(stgb + A_BYTES + dB[0],           B1p[0] + ko);                   \
        cp16(stgb + A_BYTES + dB[1],           B1p[1] + ko);                   \
        cp16(stgb + A_BYTES + B_BYTES + dB[0], B2p[0] + ko);                   \
        cp16(stgb + A_BYTES + B_BYTES + dB[1], B2p[1] + ko);                   \
    } while (0)

    G1_LOAD(0, 0); CP_COMMIT();
    G1_LOAD(1, 1); CP_COMMIT();

    for (int kt = 0; kt < KT; kt++) {
        CP_WAIT(1);
        __syncthreads();
        if (kt + 2 < KT) G1_LOAD((kt + 2) % 3, kt + 2);
        CP_COMMIT();

        uint32_t stg = sb + (uint32_t)(kt % 3) * STG1_B;
        uint32_t sA  = stg;
        uint32_t sB1 = stg + A_BYTES;
        uint32_t sB2 = stg + A_BYTES + B_BYTES;

#pragma unroll
        for (int ks = 0; ks < 4; ks++) {
            uint32_t ko = ks * 32;        // 16 halves = 32 bytes
            uint32_t a[2][4];
            LDSM_X4(a[0], sA + lmA[0] + ko);
            LDSM_X4(a[1], sA + lmA[1] + ko);
            uint32_t b1f[4][2], b2f[4][2];
#pragma unroll
            for (int p = 0; p < 2; p++) {
                uint32_t rb[4];
                LDSM_X4(rb, sB1 + lmB[p] + ko);
                b1f[2 * p][0] = rb[0]; b1f[2 * p][1] = rb[1];
                b1f[2 * p + 1][0] = rb[2]; b1f[2 * p + 1][1] = rb[3];
                LDSM_X4(rb, sB2 + lmB[p] + ko);
                b2f[2 * p][0] = rb[0]; b2f[2 * p][1] = rb[1];
                b2f[2 * p + 1][0] = rb[2]; b2f[2 * p + 1][1] = rb[3];
            }
#pragma unroll
            for (int nt = 0; nt < 4; nt++) {
#pragma unroll
                for (int mt = 0; mt < 2; mt++) {
                    MMA_F16(accA[mt][nt], a[mt], b1f[nt]);
                    MMA_F16(accU[mt][nt], a[mt], b2f[nt]);
                }
            }
        }
    }
#undef G1_LOAD

#pragma unroll
    for (int mt = 0; mt < 2; mt++) {
        int row = m0 + warpM * 32 + mt * 16 + g;
        float w0 = (row < count)     ? g_slotw[base + row]     : 0.f;
        float w1 = (row + 8 < count) ? g_slotw[base + row + 8] : 0.f;
#pragma unroll
        for (int nt = 0; nt < 4; nt++) {
            int col = n0 + warpN * 32 + nt * 8 + 2 * tig;
            if (row < count) {
                __half2 v = __floats2half2_rn(
                    w0 * silu_mul(accA[mt][nt][0], accU[mt][nt][0]),
                    w0 * silu_mul(accA[mt][nt][1], accU[mt][nt][1]));
                *(__half2*)(g_h + (size_t)(base + row) * I_DIM + col) = v;
            }
            if (row + 8 < count) {
                __half2 v = __floats2half2_rn(
                    w1 * silu_mul(accA[mt][nt][2], accU[mt][nt][2]),
                    w1 * silu_mul(accA[mt][nt][3], accU[mt][nt][3]));
                *(__half2*)(g_h + (size_t)(base + row + 8) * I_DIM + col) = v;
            }
        }
    }
}

// ----------------------------- GEMM2: 128x128 CTA, 256 thr, 2x4, 64x32 -------
__global__ __launch_bounds__(256, 2)
void gemm2_mma() {
    extern __shared__ __half sm[];
    int e = blockIdx.z;
    int base = g_off[e], count = g_off[e + 1] - base;
    int m0 = blockIdx.y * BM;
    if (m0 >= count) return;
    int n0 = blockIdx.x * 128;   // BN2 = 128

    int tid = threadIdx.x;
    int wid = tid >> 5, lane = tid & 31;
    int warpM = wid >> 2, warpN = wid & 3;   // 2x4 grid, 64x32 warp tiles
    int g = lane >> 2, tig = lane & 3;

    int r  = tid >> 3;            // 0..31
    int hc = (tid & 7) * 8;

    const __half* Ap[4];
#pragma unroll
    for (int p = 0; p < 4; p++) {
        int mm = m0 + r + 32 * p; if (mm > count - 1) mm = count - 1;
        Ap[p] = g_h + (size_t)(base + mm) * I_DIM + hc;
    }
    const __half* Bp = g_w2h + ((size_t)e * H_DIM + n0 + r) * I_DIM + hc;

    uint32_t sb = smem_u32(sm);
    uint32_t dA[4];
#pragma unroll
    for (int p = 0; p < 4; p++) dA[p] = ((r + 32 * p) * SROW2 + hc) * 2;

    uint32_t lmA[4];
#pragma unroll
    for (int mt = 0; mt < 4; mt++) {
        int row = warpM * 64 + mt * 16 + (lane & 15);
        int kh  = (lane >> 4) * 8;
        lmA[mt] = (uint32_t)(row * SROW2 + kh) * 2u;
    }
    uint32_t lmB[2];
#pragma unroll
    for (int p = 0; p < 2; p++) {
        int nrow = warpN * 32 + p * 16 + ((lane >> 4) * 8) + (lane & 7);
        int kh   = ((lane >> 3) & 1) * 8;
        lmB[p] = (uint32_t)(nrow * SROW2 + kh) * 2u;
    }

    float acc[4][4][4];
#pragma unroll
    for (int mt = 0; mt < 4; mt++)
#pragma unroll
        for (int nt = 0; nt < 4; nt++)
#pragma unroll
            for (int j = 0; j < 4; j++) acc[mt][nt][j] = 0.f;

    const int KT = I_DIM / BK;   // 22

#define G2_LOAD(s, kt) do {                                                    \
        uint32_t stgb = sb + (uint32_t)(s) * STG2_B;                           \
        int ko = (kt) * BK;                                                    \
        cp16(stgb + dA[0], Ap[0] + ko);                                        \
        cp16(stgb + dA[1], Ap[1] + ko);                                        \
        cp16(stgb + dA[2], Ap[2] + ko);                                        \
        cp16(stgb + dA[3], Ap[3] + ko);                                        \
        cp16(stgb + A_BYTES + dA[0], Bp + ko);                                 \
        cp16(stgb + A_BYTES + dA[1], Bp + 32 * I_DIM + ko);                    \
        cp16(stgb + A_BYTES + dA[2], Bp + 64 * I_DIM + ko);                    \
        cp16(stgb + A_BYTES + dA[3], Bp + 96 * I_DIM + ko);                    \
    } while (0)

    G2_LOAD(0, 0); CP_COMMIT();
    G2_LOAD(1, 1); CP_COMMIT();

    for (int kt = 0; kt < KT; kt++) {
        CP_WAIT(1);
        __syncthreads();
        if (kt + 2 < KT) G2_LOAD((kt + 2) % 3, kt + 2);
        CP_COMMIT();

        uint32_t stg = sb + (uint32_t)(kt % 3) * STG2_B;
        uint32_t sA  = stg;
        uint32_t sB  = stg + A_BYTES;

#pragma unroll
        for (int ks = 0; ks < 4; ks++) {
            uint32_t ko = ks * 32;
            uint32_t bf[4][2];
#pragma unroll
            for (int p = 0; p < 2; p++) {
                uint32_t rb[4];
                LDSM_X4(rb, sB + lmB[p] + ko);
                bf[2 * p][0] = rb[0]; bf[2 * p][1] = rb[1];
                bf[2 * p + 1][0] = rb[2]; bf[2 * p + 1][1] = rb[3];
            }
#pragma unroll
            for (int mt = 0; mt < 4; mt++) {
                uint32_t a[4];
                LDSM_X4(a, sA + lmA[mt] + ko);
#pragma unroll
                for (int nt = 0; nt < 4; nt++) MMA_F16(acc[mt][nt], a, bf[nt]);
            }
        }
    }
#undef G2_LOAD

#pragma unroll
    for (int mt = 0; mt < 4; mt++) {
#pragma unroll
        for (int nt = 0; nt < 4; nt++) {
            int row = m0 + warpM * 64 + mt * 16 + g;
            int col = n0 + warpN * 32 + nt * 8 + 2 * tig;
            if (row < count) {
                float2 v = make_float2(acc[mt][nt][0], acc[mt][nt][1]);
                *(float2*)(g_o2 + (size_t)(base + row) * H_DIM + col) = v;
            }
            if (row + 8 < count) {
                float2 v = make_float2(acc[mt][nt][2], acc[mt][nt][3]);
                *(float2*)(g_o2 + (size_t)(base + row + 8) * H_DIM + col) = v;
            }
        }
    }
}

// ----------------------------- combine ---------------------------------------
__global__ void combine_kernel(float4* __restrict__ out) {
    int idx = blockIdx.x * blockDim.x + threadIdx.x;
    int t = idx >> 9;
    int c = idx & 511;
    const float4* r0 = (const float4*)(g_o2 + (size_t)g_slot[t * 2]     * H_DIM) + c;
    const float4* r1 = (const float4*)(g_o2 + (size_t)g_slot[t * 2 + 1] * H_DIM) + c;
    float4 a = *r0, b = *r1, v;
    v.x = a.x + b.x;
    v.y = a.y + b.y;
    v.z = a.z + b.z;
    v.w = a.w + b.w;
    out[idx] = v;
}

// ----------------------------- launch -----------------------------------------
extern "C" void kernel_launch(void* const* d_in, const int* in_sizes, int n_in,
                              void* d_out, int out_size) {
    const float* x  = (const float*)d_in[0];
    const float* gw = (const float*)d_in[1];
    const float* W1 = (const float*)d_in[2];
    const float* Up = (const float*)d_in[3];
    const float* W2 = (const float*)d_in[4];
    float* out = (float*)d_out;

    const int SMEM1 = 3 * STG1_B;    // 110,592
    const int SMEM2 = 3 * STG2_B;    // 110,592
    cudaFuncSetAttribute(gemm1_mma, cudaFuncAttributeMaxDynamicSharedMemorySize, SMEM1);
    cudaFuncSetAttribute(gemm2_mma, cudaFuncAttributeMaxDynamicSharedMemorySize, SMEM2);

    prep_kernel<<<PREP_BLKS, 256>>>(x, gw, (const float4*)W1,
                                    (const float4*)Up, (const float4*)W2);      // 0
    scatter_kernel<<<1, 1024>>>();                                              // 1

    dim3 g1(I_DIM / BN, T_TOK / BM, E_NUM);          // 2: (22, 64, 16)
    gemm1_mma<<<g1, 256, SMEM1>>>();

    dim3 g2(H_DIM / 128, T_TOK / BM, E_NUM);         // 3: (16, 64, 16) <- profiled
    gemm2_mma<<<g2, 256, SMEM2>>>();

    combine_kernel<<<(T_TOK * H_DIM / 4) / 256, 256>>>((float4*)out);           // 4
}

// round 12
// speedup vs baseline: 1.1562x; 1.0165x over previous
#include <cuda_runtime.h>
#include <cuda_fp16.h>
#include <math.h>
#include <stdint.h>

#define T_TOK 8192
#define H_DIM 2048
#define I_DIM 1408
#define E_NUM 16
#define TOPK  2
#define NSLOT (T_TOK * TOPK)

#define BM 128
#define BN 64
#define BK 64                 // halves per K-slab (128 B/row)
#define SROW2 72              // padded halves per smem row (144 B)
#define A_BYTES (128 * SROW2 * 2)       // 18432 (128 rows)
#define B_BYTES (64  * SROW2 * 2)       // 9216  (64 rows)
#define STG1_B (A_BYTES + 2 * B_BYTES)  // 36864 (gemm1: A + B1 + B2)
#define STG2_B (2 * A_BYTES)            // 36864 (gemm2: A128 + B128)

#define GATE_BLKS 256
#define PREP_BLKS (GATE_BLKS + 6144)

// gemm1 grid flattening: 22*64*16 = 22528 gemm blocks + 1408 W2-cvt blocks,
// interleaved every 17th block. 1408 * 17 = 23936 total; 1408 * 16 = 22528.
#define G1_BLOCKS 23936
#define W2_N4 ((long)E_NUM * H_DIM * I_DIM / 4)   // 11,534,336 float4
#define W2_CHUNK 8192                              // float4 per cvt block (x32 iters)

// ----------------------------- device scratch --------------------------------
__device__ __half g_xh [(size_t)T_TOK * H_DIM];
__device__ __half g_w1h[(size_t)E_NUM * I_DIM * H_DIM];
__device__ __half g_uph[(size_t)E_NUM * I_DIM * H_DIM];
__device__ __half g_w2h[(size_t)E_NUM * H_DIM * I_DIM];
__device__ __half g_h  [(size_t)NSLOT * I_DIM];
__device__ float  g_o2 [(size_t)NSLOT * H_DIM];
__device__ int    g_top2[T_TOK * 2];
__device__ float  g_wts [T_TOK * 2];
__device__ int    g_off [E_NUM + 1];
__device__ int    g_tok [NSLOT];
__device__ float  g_slotw[NSLOT];
__device__ int    g_slot[T_TOK * 2];

// ----------------------------- helpers ---------------------------------------
__device__ __forceinline__ uint32_t smem_u32(const void* p) {
    uint32_t a;
    asm("{ .reg .u64 t; cvta.to.shared.u64 t, %1; cvt.u32.u64 %0, t; }" : "=r"(a) : "l"(p));
    return a;
}
__device__ __forceinline__ void cp16(uint32_t dst, const void* src) {
    asm volatile("cp.async.cg.shared.global [%0], [%1], 16;"
                 :: "r"(dst), "l"(__cvta_generic_to_global(src)) : "memory");
}
#define CP_COMMIT() asm volatile("cp.async.commit_group;" ::: "memory")
#define CP_WAIT(n)  asm volatile("cp.async.wait_group %0;" :: "n"(n) : "memory")

#define MMA_F16(d, a, b)                                                       \
    asm volatile("mma.sync.aligned.m16n8k16.row.col.f32.f16.f16.f32 "          \
        "{%0,%1,%2,%3}, {%4,%5,%6,%7}, {%8,%9}, {%0,%1,%2,%3};"                \
        : "+f"((d)[0]), "+f"((d)[1]), "+f"((d)[2]), "+f"((d)[3])               \
        : "r"((a)[0]), "r"((a)[1]), "r"((a)[2]), "r"((a)[3]),                  \
          "r"((b)[0]), "r"((b)[1]))

#define LDSM_X4(r, addr)                                                       \
    asm volatile("ldmatrix.sync.aligned.m8n8.x4.shared.b16 {%0,%1,%2,%3}, [%4];" \
        : "=r"((r)[0]), "=r"((r)[1]), "=r"((r)[2]), "=r"((r)[3]) : "r"(addr))

__device__ __forceinline__ float silu_mul(float a, float u) {
    return (a / (1.f + __expf(-a))) * u;
}
__device__ __forceinline__ void cvt4(const float4* src, __half* dst, long i) {
    float4 v = src[i];
    __half2 h01 = __floats2half2_rn(v.x, v.y);
    __half2 h23 = __floats2half2_rn(v.z, v.w);
    uint2 u;
    u.x = *(uint32_t*)&h01;
    u.y = *(uint32_t*)&h23;
    *(uint2*)(dst + i * 4) = u;
}

// ----------------------------- fused prep: gate + x->fp16 + W1/Up->fp16 ------
__global__ __launch_bounds__(256)
void prep_kernel(const float* __restrict__ x,  const float* __restrict__ gw,
                 const float4* __restrict__ w1, const float4* __restrict__ up) {
    int tid = threadIdx.x;
    if (blockIdx.x < GATE_BLKS) {
        int warp = tid >> 5, lane = tid & 31;
#pragma unroll
        for (int i = 0; i < 4; i++) {
            int t = blockIdx.x * 32 + warp * 4 + i;
            const float* xr = x + (size_t)t * H_DIM;
            float acc[E_NUM];
#pragma unroll
            for (int e = 0; e < E_NUM; e++) acc[e] = 0.f;
            for (int k = lane * 2; k < H_DIM; k += 64) {
                float2 xv = *(const float2*)(xr + k);
                __half2 hv = __floats2half2_rn(xv.x, xv.y);
                *(__half2*)(g_xh + (size_t)t * H_DIM + k) = hv;
#pragma unroll
                for (int e = 0; e < E_NUM; e++) {
                    float2 g = __ldg((const float2*)(gw + e * H_DIM + k));
                    acc[e] += xv.x * g.x + xv.y * g.y;
                }
            }
#pragma unroll
            for (int e = 0; e < E_NUM; e++) {
#pragma unroll
                for (int off = 16; off > 0; off >>= 1)
                    acc[e] += __shfl_xor_sync(0xFFFFFFFFu, acc[e], off);
            }
            if (lane == 0) {
                int e1 = 0; float l1 = acc[0];
#pragma unroll
                for (int e = 1; e < E_NUM; e++) if (acc[e] > l1) { l1 = acc[e]; e1 = e; }
                int e2 = -1; float l2 = -INFINITY;
#pragma unroll
                for (int e = 0; e < E_NUM; e++)
                    if (e != e1 && acc[e] > l2) { l2 = acc[e]; e2 = e; }
                float p2  = expf(l2 - l1);
                float inv = 1.f / (1.f + p2);
                g_top2[t * 2] = e1; g_top2[t * 2 + 1] = e2;
                g_wts[t * 2] = inv; g_wts[t * 2 + 1] = p2 * inv;
            }
        }
    } else {
        // W1 + Up fp32 -> fp16 (W2 handled inside gemm1 launch)
        const long n4 = (long)E_NUM * I_DIM * H_DIM / 4;
        long i = (long)(blockIdx.x - GATE_BLKS) * 256 + tid;
        long stride = (long)(PREP_BLKS - GATE_BLKS) * 256;
        for (; i < 2 * n4; i += stride) {
            if (i < n4) cvt4(w1, g_w1h, i);
            else        cvt4(up, g_uph, i - n4);   // both src AND dst at j = i - n4
        }
    }
}

// ----------------------------- scatter ----------------------------------------
__global__ __launch_bounds__(1024)
void scatter_kernel() {
    __shared__ int s_cnt[E_NUM];
    __shared__ int s_fill[E_NUM];
    int tid = threadIdx.x;
    if (tid < E_NUM) { s_cnt[tid] = 0; s_fill[tid] = 0; }
    __syncthreads();
    for (int t = tid; t < T_TOK; t += 1024) {
        atomicAdd(&s_cnt[g_top2[t * 2]], 1);
        atomicAdd(&s_cnt[g_top2[t * 2 + 1]], 1);
    }
    __syncthreads();
    if (tid == 0) {
        int s = 0;
        for (int e = 0; e < E_NUM; e++) { g_off[e] = s; s += s_cnt[e]; }
        g_off[E_NUM] = s;
    }
    __syncthreads();
    for (int t = tid; t < T_TOK; t += 1024) {
#pragma unroll
        for (int kk = 0; kk < TOPK; kk++) {
            int e = g_top2[t * 2 + kk];
            int p = atomicAdd(&s_fill[e], 1);
            int slot = g_off[e] + p;
            g_tok[slot]   = t;
            g_slotw[slot] = g_wts[t * 2 + kk];
            g_slot[t * 2 + kk] = slot;
        }
    }
}

// ------------- GEMM1 (256 thr, 4x2 warps, 32x32 dual) + embedded W2 cvt ------
__global__ __launch_bounds__(256, 2)
void gemm1_mma(const float4* __restrict__ w2src) {
    int bid = blockIdx.x;
    int mod = bid % 17;
    if (mod == 16) {
        // interleaved W2 fp32 -> fp16 block: 8192 float4 (x32 iters of 256 thr)
        long i0 = (long)(bid / 17) * W2_CHUNK + threadIdx.x;
#pragma unroll 4
        for (int it = 0; it < 32; it++) cvt4(w2src, g_w2h, i0 + it * 256);
        return;
    }
    int gidx = (bid / 17) * 16 + mod;       // 0 .. 22527
    int e  = gidx / (22 * 64);
    int m0 = ((gidx / 22) % 64) * BM;
    int n0 = (gidx % 22) * BN;

    extern __shared__ __half sm[];
    int base = g_off[e], count = g_off[e + 1] - base;
    if (m0 >= count) return;

    int tid = threadIdx.x;
    int wid = tid >> 5, lane = tid & 31;
    int warpM = wid >> 1, warpN = wid & 1;
    int g = lane >> 2, tig = lane & 3;

    int r  = tid >> 3;            // 0..31
    int hc = (tid & 7) * 8;

    const __half* Ap[4];
#pragma unroll
    for (int p = 0; p < 4; p++) {
        int mm = m0 + r + 32 * p; if (mm > count - 1) mm = count - 1;
        Ap[p] = g_xh + (size_t)g_tok[base + mm] * H_DIM + hc;
    }
    const __half* B1p[2];
    const __half* B2p[2];
#pragma unroll
    for (int p = 0; p < 2; p++) {
        int nn = n0 + r + 32 * p;
        B1p[p] = g_w1h + ((size_t)e * I_DIM + nn) * H_DIM + hc;
        B2p[p] = g_uph + ((size_t)e * I_DIM + nn) * H_DIM + hc;
    }

    uint32_t sb = smem_u32(sm);
    uint32_t dA[4], dB[2];
#pragma unroll
    for (int p = 0; p < 4; p++) dA[p] = ((r + 32 * p) * SROW2 + hc) * 2;
#pragma unroll
    for (int p = 0; p < 2; p++) dB[p] = ((r + 32 * p) * SROW2 + hc) * 2;

    uint32_t lmA[2];
#pragma unroll
    for (int mt = 0; mt < 2; mt++) {
        int row = warpM * 32 + mt * 16 + (lane & 15);
        int kh  = (lane >> 4) * 8;
        lmA[mt] = (uint32_t)(row * SROW2 + kh) * 2u;
    }
    uint32_t lmB[2];
#pragma unroll
    for (int p = 0; p < 2; p++) {
        int nrow = warpN * 32 + p * 16 + ((lane >> 4) * 8) + (lane & 7);
        int kh   = ((lane >> 3) & 1) * 8;
        lmB[p] = (uint32_t)(nrow * SROW2 + kh) * 2u;
    }

    float accA[2][4][4], accU[2][4][4];
#pragma unroll
    for (int mt = 0; mt < 2; mt++)
#pragma unroll
        for (int nt = 0; nt < 4; nt++)
#pragma unroll
            for (int j = 0; j < 4; j++) { accA[mt][nt][j] = 0.f; accU[mt][nt][j] = 0.f; }

    const int KT = H_DIM / BK;   // 32

#define G1_LOAD(s, kt) do {                                                    \
        uint32_t stgb = sb + (uint32_t)(s) * STG1_B;                           \
        int ko = (kt) * BK;                                                    \
        cp16(stgb + dA[0],                     Ap[0]  + ko);                   \
        cp16(stgb + dA[1],                     Ap[1]  + ko);                   \
        cp16(stgb + dA[2],                     Ap[2]  + ko);                   \
        cp16(stgb + dA[3],                     Ap[3]  + ko);                   \
        cp16(stgb + A_BYTES + dB[0],           B1p[0] + ko);                   \
        cp16(stgb + A_BYTES + dB[1],           B1p[1] + ko);                   \
        cp16(stgb + A_BYTES + B_BYTES + dB[0], B2p[0] + ko);                   \
        cp16(stgb + A_BYTES + B_BYTES + dB[1], B2p[1] + ko);                   \
    } while (0)

    G1_LOAD(0, 0); CP_COMMIT();
    G1_LOAD(1, 1); CP_COMMIT();

    for (int kt = 0; kt < KT; kt++) {
        CP_WAIT(1);
        __syncthreads();
        if (kt + 2 < KT) G1_LOAD((kt + 2) % 3, kt + 2);
        CP_COMMIT();

        uint32_t stg = sb + (uint32_t)(kt % 3) * STG1_B;
        uint32_t sA  = stg;
        uint32_t sB1 = stg + A_BYTES;
        uint32_t sB2 = stg + A_BYTES + B_BYTES;

#pragma unroll
        for (int ks = 0; ks < 4; ks++) {
            uint32_t ko = ks * 32;        // 16 halves = 32 bytes
            uint32_t a[2][4];
            LDSM_X4(a[0], sA + lmA[0] + ko);
            LDSM_X4(a[1], sA + lmA[1] + ko);
            uint32_t b1f[4][2], b2f[4][2];
#pragma unroll
            for (int p = 0; p < 2; p++) {
                uint32_t rb[4];
                LDSM_X4(rb, sB1 + lmB[p] + ko);
                b1f[2 * p][0] = rb[0]; b1f[2 * p][1] = rb[1];
                b1f[2 * p + 1][0] = rb[2]; b1f[2 * p + 1][1] = rb[3];
                LDSM_X4(rb, sB2 + lmB[p] + ko);
                b2f[2 * p][0] = rb[0]; b2f[2 * p][1] = rb[1];
                b2f[2 * p + 1][0] = rb[2]; b2f[2 * p + 1][1] = rb[3];
            }
#pragma unroll
            for (int nt = 0; nt < 4; nt++) {
#pragma unroll
                for (int mt = 0; mt < 2; mt++) {
                    MMA_F16(accA[mt][nt], a[mt], b1f[nt]);
                    MMA_F16(accU[mt][nt], a[mt], b2f[nt]);
                }
            }
        }
    }
#undef G1_LOAD

#pragma unroll
    for (int mt = 0; mt < 2; mt++) {
        int row = m0 + warpM * 32 + mt * 16 + g;
        float w0 = (row < count)     ? g_slotw[base + row]     : 0.f;
        float w1 = (row + 8 < count) ? g_slotw[base + row + 8] : 0.f;
#pragma unroll
        for (int nt = 0; nt < 4; nt++) {
            int col = n0 + warpN * 32 + nt * 8 + 2 * tig;
            if (row < count) {
                __half2 v = __floats2half2_rn(
                    w0 * silu_mul(accA[mt][nt][0], accU[mt][nt][0]),
                    w0 * silu_mul(accA[mt][nt][1], accU[mt][nt][1]));
                *(__half2*)(g_h + (size_t)(base + row) * I_DIM + col) = v;
            }
            if (row + 8 < count) {
                __half2 v = __floats2half2_rn(
                    w1 * silu_mul(accA[mt][nt][2], accU[mt][nt][2]),
                    w1 * silu_mul(accA[mt][nt][3], accU[mt][nt][3]));
                *(__half2*)(g_h + (size_t)(base + row + 8) * I_DIM + col) = v;
            }
        }
    }
}

// ----------------------------- GEMM2: 128x128 CTA, 256 thr, 2x4, 64x32 -------
__global__ __launch_bounds__(256, 2)
void gemm2_mma() {
    extern __shared__ __half sm[];
    int e = blockIdx.z;
    int base = g_off[e], count = g_off[e + 1] - base;
    int m0 = blockIdx.y * BM;
    if (m0 >= count) return;
    int n0 = blockIdx.x * 128;   // BN2 = 128

    int tid = threadIdx.x;
    int wid = tid >> 5, lane = tid & 31;
    int warpM = wid >> 2, warpN = wid & 3;   // 2x4 grid, 64x32 warp tiles
    int g = lane >> 2, tig = lane & 3;

    int r  = tid >> 3;            // 0..31
    int hc = (tid & 7) * 8;

    const __half* Ap[4];
#pragma unroll
    for (int p = 0; p < 4; p++) {
        int mm = m0 + r + 32 * p; if (mm > count - 1) mm = count - 1;
        Ap[p] = g_h + (size_t)(base + mm) * I_DIM + hc;
    }
    const __half* Bp = g_w2h + ((size_t)e * H_DIM + n0 + r) * I_DIM + hc;

    uint32_t sb = smem_u32(sm);
    uint32_t dA[4];
#pragma unroll
    for (int p = 0; p < 4; p++) dA[p] = ((r + 32 * p) * SROW2 + hc) * 2;

    uint32_t lmA[4];
#pragma unroll
    for (int mt = 0; mt < 4; mt++) {
        int row = warpM * 64 + mt * 16 + (lane & 15);
        int kh  = (lane >> 4) * 8;
        lmA[mt] = (uint32_t)(row * SROW2 + kh) * 2u;
    }
    uint32_t lmB[2];
#pragma unroll
    for (int p = 0; p < 2; p++) {
        int nrow = warpN * 32 + p * 16 + ((lane >> 4) * 8) + (lane & 7);
        int kh   = ((lane >> 3) & 1) * 8;
        lmB[p] = (uint32_t)(nrow * SROW2 + kh) * 2u;
    }

    float acc[4][4][4];
#pragma unroll
    for (int mt = 0; mt < 4; mt++)
#pragma unroll
        for (int nt = 0; nt < 4; nt++)
#pragma unroll
            for (int j = 0; j < 4; j++) acc[mt][nt][j] = 0.f;

    const int KT = I_DIM / BK;   // 22

#define G2_LOAD(s, kt) do {                                                    \
        uint32_t stgb = sb + (uint32_t)(s) * STG2_B;                           \
        int ko = (kt) * BK;                                                    \
        cp16(stgb + dA[0], Ap[0] + ko);                                        \
        cp16(stgb + dA[1], Ap[1] + ko);                                        \
        cp16(stgb + dA[2], Ap[2] + ko);                                        \
        cp16(stgb + dA[3], Ap[3] + ko);                                        \
        cp16(stgb + A_BYTES + dA[0], Bp + ko);                                 \
        cp16(stgb + A_BYTES + dA[1], Bp + 32 * I_DIM + ko);                    \
        cp16(stgb + A_BYTES + dA[2], Bp + 64 * I_DIM + ko);                    \
        cp16(stgb + A_BYTES + dA[3], Bp + 96 * I_DIM + ko);                    \
    } while (0)

    G2_LOAD(0, 0); CP_COMMIT();
    G2_LOAD(1, 1); CP_COMMIT();

    for (int kt = 0; kt < KT; kt++) {
        CP_WAIT(1);
        __syncthreads();
        if (kt + 2 < KT) G2_LOAD((kt + 2) % 3, kt + 2);
        CP_COMMIT();

        uint32_t stg = sb + (uint32_t)(kt % 3) * STG2_B;
        uint32_t sA  = stg;
        uint32_t sB  = stg + A_BYTES;

#pragma unroll
        for (int ks = 0; ks < 4; ks++) {
            uint32_t ko = ks * 32;
            uint32_t bf[4][2];
#pragma unroll
            for (int p = 0; p < 2; p++) {
                uint32_t rb[4];
                LDSM_X4(rb, sB + lmB[p] + ko);
                bf[2 * p][0] = rb[0]; bf[2 * p][1] = rb[1];
                bf[2 * p + 1][0] = rb[2]; bf[2 * p + 1][1] = rb[3];
            }
#pragma unroll
            for (int mt = 0; mt < 4; mt++) {
                uint32_t a[4];
                LDSM_X4(a, sA + lmA[mt] + ko);
#pragma unroll
                for (int nt = 0; nt < 4; nt++) MMA_F16(acc[mt][nt], a, bf[nt]);
            }
        }
    }
#undef G2_LOAD

#pragma unroll
    for (int mt = 0; mt < 4; mt++) {
#pragma unroll
        for (int nt = 0; nt < 4; nt++) {
            int row = m0 + warpM * 64 + mt * 16 + g;
            int col = n0 + warpN * 32 + nt * 8 + 2 * tig;
            if (row < count) {
                float2 v = make_float2(acc[mt][nt][0], acc[mt][nt][1]);
                *(float2*)(g_o2 + (size_t)(base + row) * H_DIM + col) = v;
            }
            if (row + 8 < count) {
                float2 v = make_float2(acc[mt][nt][2], acc[mt][nt][3]);
                *(float2*)(g_o2 + (size_t)(base + row + 8) * H_DIM + col) = v;
            }
        }
    }
}

// ----------------------------- combine ---------------------------------------
__global__ void combine_kernel(float4* __restrict__ out) {
    int idx = blockIdx.x * blockDim.x + threadIdx.x;
    int t = idx >> 9;
    int c = idx & 511;
    const float4* r0 = (const float4*)(g_o2 + (size_t)g_slot[t * 2]     * H_DIM) + c;
    const float4* r1 = (const float4*)(g_o2 + (size_t)g_slot[t * 2 + 1] * H_DIM) + c;
    float4 a = *r0, b = *r1, v;
    v.x = a.x + b.x;
    v.y = a.y + b.y;
    v.z = a.z + b.z;
    v.w = a.w + b.w;
    out[idx] = v;
}

// ----------------------------- launch -----------------------------------------
extern "C" void kernel_launch(void* const* d_in, const int* in_sizes, int n_in,
                              void* d_out, int out_size) {
    const float* x  = (const float*)d_in[0];
    const float* gw = (const float*)d_in[1];
    const float* W1 = (const float*)d_in[2];
    const float* Up = (const float*)d_in[3];
    const float* W2 = (const float*)d_in[4];
    float* out = (float*)d_out;

    const int SMEM1 = 3 * STG1_B;    // 110,592
    const int SMEM2 = 3 * STG2_B;    // 110,592
    cudaFuncSetAttribute(gemm1_mma, cudaFuncAttributeMaxDynamicSharedMemorySize, SMEM1);
    cudaFuncSetAttribute(gemm2_mma, cudaFuncAttributeMaxDynamicSharedMemorySize, SMEM2);

    prep_kernel<<<PREP_BLKS, 256>>>(x, gw, (const float4*)W1, (const float4*)Up); // 0
    scatter_kernel<<<1, 1024>>>();                                                // 1

    gemm1_mma<<<G1_BLOCKS, 256, SMEM1>>>((const float4*)W2);                      // 2

    dim3 g2(H_DIM / 128, T_TOK / BM, E_NUM);         // 3: (16, 64, 16) <- profiled
    gemm2_mma<<<g2, 256, SMEM2>>>();

    combine_kernel<<<(T_TOK * H_DIM / 4) / 256, 256>>>((float4*)out);             // 4
}

// round 13
// speedup vs baseline: 1.1822x; 1.0225x over previous
#include <cuda_runtime.h>
#include <cuda_fp16.h>
#include <math.h>
#include <stdint.h>

#define T_TOK 8192
#define H_DIM 2048
#define I_DIM 1408
#define E_NUM 16
#define TOPK  2
#define NSLOT (T_TOK * TOPK)

#define BM 128
#define BN 64
#define BK 64                 // halves per K-slab (128 B/row)
#define SROW2 72              // padded halves per smem row (144 B)
#define A_BYTES (128 * SROW2 * 2)       // 18432 (128 rows)
#define B_BYTES (64  * SROW2 * 2)       // 9216  (64 rows)
#define STG1_B (A_BYTES + 2 * B_BYTES)  // 36864 (gemm1: A + B1 + B2)
#define STG2_B (2 * A_BYTES)            // 36864 (gemm2: A128 + B128)

#define GATE_BLKS 256
#define PREP_BLKS (GATE_BLKS + 6144)

// Compact gemm1 grid: period-13 interleave of gemm slots (9) and W2-cvt slots (4).
// 352 periods: 3168 gemm slots (>= 143*22 = 3146), 1408 cvt chunks (exact).
#define G1_BLOCKS (352 * 13)                       // 4576
#define MAX_TILES 160                              // >= 143 worst case
#define W2_N4 ((long)E_NUM * H_DIM * I_DIM / 4)    // 11,534,336 float4
#define W2_CHUNK 8192                              // float4 per cvt chunk (x32 iters)

// ----------------------------- device scratch --------------------------------
__device__ __half g_xh [(size_t)T_TOK * H_DIM];
__device__ __half g_w1h[(size_t)E_NUM * I_DIM * H_DIM];
__device__ __half g_uph[(size_t)E_NUM * I_DIM * H_DIM];
__device__ __half g_w2h[(size_t)E_NUM * H_DIM * I_DIM];
__device__ __half g_h  [(size_t)NSLOT * I_DIM];
__device__ __half g_o2 [(size_t)NSLOT * H_DIM];    // fp16 per-slot GEMM2 output
__device__ int    g_top2[T_TOK * 2];
__device__ float  g_wts [T_TOK * 2];
__device__ int    g_off [E_NUM + 1];
__device__ int    g_tok [NSLOT];
__device__ float  g_slotw[NSLOT];
__device__ int    g_slot[T_TOK * 2];
__device__ int    g_tile_e [MAX_TILES];
__device__ int    g_tile_m0[MAX_TILES];
__device__ int    g_ntile;

// ----------------------------- helpers ---------------------------------------
__device__ __forceinline__ uint32_t smem_u32(const void* p) {
    uint32_t a;
    asm("{ .reg .u64 t; cvta.to.shared.u64 t, %1; cvt.u32.u64 %0, t; }" : "=r"(a) : "l"(p));
    return a;
}
__device__ __forceinline__ void cp16(uint32_t dst, const void* src) {
    asm volatile("cp.async.cg.shared.global [%0], [%1], 16;"
                 :: "r"(dst), "l"(__cvta_generic_to_global(src)) : "memory");
}
#define CP_COMMIT() asm volatile("cp.async.commit_group;" ::: "memory")
#define CP_WAIT(n)  asm volatile("cp.async.wait_group %0;" :: "n"(n) : "memory")

#define MMA_F16(d, a, b)                                                       \
    asm volatile("mma.sync.aligned.m16n8k16.row.col.f32.f16.f16.f32 "          \
        "{%0,%1,%2,%3}, {%4,%5,%6,%7}, {%8,%9}, {%0,%1,%2,%3};"                \
        : "+f"((d)[0]), "+f"((d)[1]), "+f"((d)[2]), "+f"((d)[3])               \
        : "r"((a)[0]), "r"((a)[1]), "r"((a)[2]), "r"((a)[3]),                  \
          "r"((b)[0]), "r"((b)[1]))

#define LDSM_X4(r, addr)                                                       \
    asm volatile("ldmatrix.sync.aligned.m8n8.x4.shared.b16 {%0,%1,%2,%3}, [%4];" \
        : "=r"((r)[0]), "=r"((r)[1]), "=r"((r)[2]), "=r"((r)[3]) : "r"(addr))

__device__ __forceinline__ float silu_mul(float a, float u) {
    return (a / (1.f + __expf(-a))) * u;
}
__device__ __forceinline__ void cvt4(const float4* src, __half* dst, long i) {
    float4 v = src[i];
    __half2 h01 = __floats2half2_rn(v.x, v.y);
    __half2 h23 = __floats2half2_rn(v.z, v.w);
    uint2 u;
    u.x = *(uint32_t*)&h01;
    u.y = *(uint32_t*)&h23;
    *(uint2*)(dst + i * 4) = u;
}

// ----------------------------- fused prep: gate + x->fp16 + W1/Up->fp16 ------
__global__ __launch_bounds__(256)
void prep_kernel(const float* __restrict__ x,  const float* __restrict__ gw,
                 const float4* __restrict__ w1, const float4* __restrict__ up) {
    int tid = threadIdx.x;
    if (blockIdx.x < GATE_BLKS) {
        int warp = tid >> 5, lane = tid & 31;
#pragma unroll
        for (int i = 0; i < 4; i++) {
            int t = blockIdx.x * 32 + warp * 4 + i;
            const float* xr = x + (size_t)t * H_DIM;
            float acc[E_NUM];
#pragma unroll
            for (int e = 0; e < E_NUM; e++) acc[e] = 0.f;
            for (int k = lane * 2; k < H_DIM; k += 64) {
                float2 xv = *(const float2*)(xr + k);
                __half2 hv = __floats2half2_rn(xv.x, xv.y);
                *(__half2*)(g_xh + (size_t)t * H_DIM + k) = hv;
#pragma unroll
                for (int e = 0; e < E_NUM; e++) {
                    float2 g = __ldg((const float2*)(gw + e * H_DIM + k));
                    acc[e] += xv.x * g.x + xv.y * g.y;
                }
            }
#pragma unroll
            for (int e = 0; e < E_NUM; e++) {
#pragma unroll
                for (int off = 16; off > 0; off >>= 1)
                    acc[e] += __shfl_xor_sync(0xFFFFFFFFu, acc[e], off);
            }
            if (lane == 0) {
                int e1 = 0; float l1 = acc[0];
#pragma unroll
                for (int e = 1; e < E_NUM; e++) if (acc[e] > l1) { l1 = acc[e]; e1 = e; }
                int e2 = -1; float l2 = -INFINITY;
#pragma unroll
                for (int e = 0; e < E_NUM; e++)
                    if (e != e1 && acc[e] > l2) { l2 = acc[e]; e2 = e; }
                float p2  = expf(l2 - l1);
                float inv = 1.f / (1.f + p2);
                g_top2[t * 2] = e1; g_top2[t * 2 + 1] = e2;
                g_wts[t * 2] = inv; g_wts[t * 2 + 1] = p2 * inv;
            }
        }
    } else {
        const long n4 = (long)E_NUM * I_DIM * H_DIM / 4;
        long i = (long)(blockIdx.x - GATE_BLKS) * 256 + tid;
        long stride = (long)(PREP_BLKS - GATE_BLKS) * 256;
        for (; i < 2 * n4; i += stride) {
            if (i < n4) cvt4(w1, g_w1h, i);
            else        cvt4(up, g_uph, i - n4);
        }
    }
}

// ----------------------------- scatter + tile table ---------------------------
__global__ __launch_bounds__(1024)
void scatter_kernel() {
    __shared__ int s_cnt[E_NUM];
    __shared__ int s_fill[E_NUM];
    int tid = threadIdx.x;
    if (tid < E_NUM) { s_cnt[tid] = 0; s_fill[tid] = 0; }
    __syncthreads();
    for (int t = tid; t < T_TOK; t += 1024) {
        atomicAdd(&s_cnt[g_top2[t * 2]], 1);
        atomicAdd(&s_cnt[g_top2[t * 2 + 1]], 1);
    }
    __syncthreads();
    if (tid == 0) {
        int s = 0;
        for (int e = 0; e < E_NUM; e++) { g_off[e] = s; s += s_cnt[e]; }
        g_off[E_NUM] = s;
        int nt = 0;
        for (int e = 0; e < E_NUM; e++) {
            int c = s_cnt[e];
            for (int m0 = 0; m0 < c; m0 += BM) {
                g_tile_e[nt] = e;
                g_tile_m0[nt] = m0;
                nt++;
            }
        }
        g_ntile = nt;
    }
    __syncthreads();
    for (int t = tid; t < T_TOK; t += 1024) {
#pragma unroll
        for (int kk = 0; kk < TOPK; kk++) {
            int e = g_top2[t * 2 + kk];
            int p = atomicAdd(&s_fill[e], 1);
            int slot = g_off[e] + p;
            g_tok[slot]   = t;
            g_slotw[slot] = g_wts[t * 2 + kk];
            g_slot[t * 2 + kk] = slot;
        }
    }
}

// ------- GEMM1 (256 thr, 4x2 warps, 32x32 dual) + embedded W2 cvt, compact ---
__global__ __launch_bounds__(256, 2)
void gemm1_mma(const float4* __restrict__ w2src) {
    int bid = blockIdx.x;
    int per = bid / 13, mod = bid % 13;
    if (mod >= 9) {
        // W2 fp32 -> fp16 chunk: 8192 float4 (x32 iters of 256 thr)
        long chunk = (long)per * 4 + (mod - 9);          // 0..1407, exact cover
        long i0 = chunk * W2_CHUNK + threadIdx.x;
#pragma unroll 4
        for (int it = 0; it < 32; it++) cvt4(w2src, g_w2h, i0 + it * 256);
        return;
    }
    int gi = per * 9 + mod;                  // 0..3167
    int tile = gi / 22;
    if (tile >= g_ntile) return;
    int e  = g_tile_e[tile];
    int m0 = g_tile_m0[tile];
    int n0 = (gi % 22) * BN;

    extern __shared__ __half sm[];
    int base = g_off[e], count = g_off[e + 1] - base;

    int tid = threadIdx.x;
    int wid = tid >> 5, lane = tid & 31;
    int warpM = wid >> 1, warpN = wid & 1;
    int g = lane >> 2, tig = lane & 3;

    int r  = tid >> 3;            // 0..31
    int hc = (tid & 7) * 8;

    const __half* Ap[4];
#pragma unroll
    for (int p = 0; p < 4; p++) {
        int mm = m0 + r + 32 * p; if (mm > count - 1) mm = count - 1;
        Ap[p] = g_xh + (size_t)g_tok[base + mm] * H_DIM + hc;
    }
    const __half* B1p[2];
    const __half* B2p[2];
#pragma unroll
    for (int p = 0; p < 2; p++) {
        int nn = n0 + r + 32 * p;
        B1p[p] = g_w1h + ((size_t)e * I_DIM + nn) * H_DIM + hc;
        B2p[p] = g_uph + ((size_t)e * I_DIM + nn) * H_DIM + hc;
    }

    uint32_t sb = smem_u32(sm);
    uint32_t dA[4], dB[2];
#pragma unroll
    for (int p = 0; p < 4; p++) dA[p] = ((r + 32 * p) * SROW2 + hc) * 2;
#pragma unroll
    for (int p = 0; p < 2; p++) dB[p] = ((r + 32 * p) * SROW2 + hc) * 2;

    uint32_t lmA[2];
#pragma unroll
    for (int mt = 0; mt < 2; mt++) {
        int row = warpM * 32 + mt * 16 + (lane & 15);
        int kh  = (lane >> 4) * 8;
        lmA[mt] = (uint32_t)(row * SROW2 + kh) * 2u;
    }
    uint32_t lmB[2];
#pragma unroll
    for (int p = 0; p < 2; p++) {
        int nrow = warpN * 32 + p * 16 + ((lane >> 4) * 8) + (lane & 7);
        int kh   = ((lane >> 3) & 1) * 8;
        lmB[p] = (uint32_t)(nrow * SROW2 + kh) * 2u;
    }

    float accA[2][4][4], accU[2][4][4];
#pragma unroll
    for (int mt = 0; mt < 2; mt++)
#pragma unroll
        for (int nt = 0; nt < 4; nt++)
#pragma unroll
            for (int j = 0; j < 4; j++) { accA[mt][nt][j] = 0.f; accU[mt][nt][j] = 0.f; }

    const int KT = H_DIM / BK;   // 32

#define G1_LOAD(s, kt) do {                                                    \
        uint32_t stgb = sb + (uint32_t)(s) * STG1_B;                           \
        int ko = (kt) * BK;                                                    \
        cp16(stgb + dA[0],                     Ap[0]  + ko);                   \
        cp16(stgb + dA[1],                     Ap[1]  + ko);                   \
        cp16(stgb + dA[2],                     Ap[2]  + ko);                   \
        cp16(stgb + dA[3],                     Ap[3]  + ko);                   \
        cp16(stgb + A_BYTES + dB[0],           B1p[0] + ko);                   \
        cp16(stgb + A_BYTES + dB[1],           B1p[1] + ko);                   \
        cp16(stgb + A_BYTES + B_BYTES + dB[0], B2p[0] + ko);                   \
        cp16(stgb + A_BYTES + B_BYTES + dB[1], B2p[1] + ko);                   \
    } while (0)

    G1_LOAD(0, 0); CP_COMMIT();
    G1_LOAD(1, 1); CP_COMMIT();

    for (int kt = 0; kt < KT; kt++) {
        CP_WAIT(1);
        __syncthreads();
        if (kt + 2 < KT) G1_LOAD((kt + 2) % 3, kt + 2);
        CP_COMMIT();

        uint32_t stg = sb + (uint32_t)(kt % 3) * STG1_B;
        uint32_t sA  = stg;
        uint32_t sB1 = stg + A_BYTES;
        uint32_t sB2 = stg + A_BYTES + B_BYTES;

#pragma unroll
        for (int ks = 0; ks < 4; ks++) {
            uint32_t ko = ks * 32;        // 16 halves = 32 bytes
            uint32_t a[2][4];
            LDSM_X4(a[0], sA + lmA[0] + ko);
            LDSM_X4(a[1], sA + lmA[1] + ko);
            uint32_t b1f[4][2], b2f[4][2];
#pragma unroll
            for (int p = 0; p < 2; p++) {
                uint32_t rb[4];
                LDSM_X4(rb, sB1 + lmB[p] + ko);
                b1f[2 * p][0] = rb[0]; b1f[2 * p][1] = rb[1];
                b1f[2 * p + 1][0] = rb[2]; b1f[2 * p + 1][1] = rb[3];
                LDSM_X4(rb, sB2 + lmB[p] + ko);
                b2f[2 * p][0] = rb[0]; b2f[2 * p][1] = rb[1];
                b2f[2 * p + 1][0] = rb[2]; b2f[2 * p + 1][1] = rb[3];
            }
#pragma unroll
            for (int nt = 0; nt < 4; nt++) {
#pragma unroll
                for (int mt = 0; mt < 2; mt++) {
                    MMA_F16(accA[mt][nt], a[mt], b1f[nt]);
                    MMA_F16(accU[mt][nt], a[mt], b2f[nt]);
                }
            }
        }
    }
#undef G1_LOAD

#pragma unroll
    for (int mt = 0; mt < 2; mt++) {
        int row = m0 + warpM * 32 + mt * 16 + g;
        float w0 = (row < count)     ? g_slotw[base + row]     : 0.f;
        float w1 = (row + 8 < count) ? g_slotw[base + row + 8] : 0.f;
#pragma unroll
        for (int nt = 0; nt < 4; nt++) {
            int col = n0 + warpN * 32 + nt * 8 + 2 * tig;
            if (row < count) {
                __half2 v = __floats2half2_rn(
                    w0 * silu_mul(accA[mt][nt][0], accU[mt][nt][0]),
                    w0 * silu_mul(accA[mt][nt][1], accU[mt][nt][1]));
                *(__half2*)(g_h + (size_t)(base + row) * I_DIM + col) = v;
            }
            if (row + 8 < count) {
                __half2 v = __floats2half2_rn(
                    w1 * silu_mul(accA[mt][nt][2], accU[mt][nt][2]),
                    w1 * silu_mul(accA[mt][nt][3], accU[mt][nt][3]));
                *(__half2*)(g_h + (size_t)(base + row + 8) * I_DIM + col) = v;
            }
        }
    }
}

// --------- GEMM2: 128x128 CTA, 256 thr, 2x4, 64x32, compact grid, fp16 out ---
__global__ __launch_bounds__(256, 2)
void gemm2_mma() {
    int tile = blockIdx.x >> 4;
    if (tile >= g_ntile) return;
    int e  = g_tile_e[tile];
    int m0 = g_tile_m0[tile];
    int n0 = (blockIdx.x & 15) * 128;   // BN2 = 128

    extern __shared__ __half sm[];
    int base = g_off[e], count = g_off[e + 1] - base;

    int tid = threadIdx.x;
    int wid = tid >> 5, lane = tid & 31;
    int warpM = wid >> 2, warpN = wid & 3;   // 2x4 grid, 64x32 warp tiles
    int g = lane >> 2, tig = lane & 3;

    int r  = tid >> 3;            // 0..31
    int hc = (tid & 7) * 8;

    const __half* Ap[4];
#pragma unroll
    for (int p = 0; p < 4; p++) {
        int mm = m0 + r + 32 * p; if (mm > count - 1) mm = count - 1;
        Ap[p] = g_h + (size_t)(base + mm) * I_DIM + hc;
    }
    const __half* Bp = g_w2h + ((size_t)e * H_DIM + n0 + r) * I_DIM + hc;

    uint32_t sb = smem_u32(sm);
    uint32_t dA[4];
#pragma unroll
    for (int p = 0; p < 4; p++) dA[p] = ((r + 32 * p) * SROW2 + hc) * 2;

    uint32_t lmA[4];
#pragma unroll
    for (int mt = 0; mt < 4; mt++) {
        int row = warpM * 64 + mt * 16 + (lane & 15);
        int kh  = (lane >> 4) * 8;
        lmA[mt] = (uint32_t)(row * SROW2 + kh) * 2u;
    }
    uint32_t lmB[2];
#pragma unroll
    for (int p = 0; p < 2; p++) {
        int nrow = warpN * 32 + p * 16 + ((lane >> 4) * 8) + (lane & 7);
        int kh   = ((lane >> 3) & 1) * 8;
        lmB[p] = (uint32_t)(nrow * SROW2 + kh) * 2u;
    }

    float acc[4][4][4];
#pragma unroll
    for (int mt = 0; mt < 4; mt++)
#pragma unroll
        for (int nt = 0; nt < 4; nt++)
#pragma unroll
            for (int j = 0; j < 4; j++) acc[mt][nt][j] = 0.f;

    const int KT = I_DIM / BK;   // 22

#define G2_LOAD(s, kt) do {                                                    \
        uint32_t stgb = sb + (uint32_t)(s) * STG2_B;                           \
        int ko = (kt) * BK;                                                    \
        cp16(stgb + dA[0], Ap[0] + ko);                                        \
        cp16(stgb + dA[1], Ap[1] + ko);                                        \
        cp16(stgb + dA[2], Ap[2] + ko);                                        \
        cp16(stgb + dA[3], Ap[3] + ko);                                        \
        cp16(stgb + A_BYTES + dA[0], Bp + ko);                                 \
        cp16(stgb + A_BYTES + dA[1], Bp + 32 * I_DIM + ko);                    \
        cp16(stgb + A_BYTES + dA[2], Bp + 64 * I_DIM + ko);                    \
        cp16(stgb + A_BYTES + dA[3], Bp + 96 * I_DIM + ko);                    \
    } while (0)

    G2_LOAD(0, 0); CP_COMMIT();
    G2_LOAD(1, 1); CP_COMMIT();

    for (int kt = 0; kt < KT; kt++) {
        CP_WAIT(1);
        __syncthreads();
        if (kt + 2 < KT) G2_LOAD((kt + 2) % 3, kt + 2);
        CP_COMMIT();

        uint32_t stg = sb + (uint32_t)(kt % 3) * STG2_B;
        uint32_t sA  = stg;
        uint32_t sB  = stg + A_BYTES;

#pragma unroll
        for (int ks = 0; ks < 4; ks++) {
            uint32_t ko = ks * 32;
            uint32_t bf[4][2];
#pragma unroll
            for (int p = 0; p < 2; p++) {
                uint32_t rb[4];
                LDSM_X4(rb, sB + lmB[p] + ko);
                bf[2 * p][0] = rb[0]; bf[2 * p][1] = rb[1];
                bf[2 * p + 1][0] = rb[2]; bf[2 * p + 1][1] = rb[3];
            }
#pragma unroll
            for (int mt = 0; mt < 4; mt++) {
                uint32_t a[4];
                LDSM_X4(a, sA + lmA[mt] + ko);
#pragma unroll
                for (int nt = 0; nt < 4; nt++) MMA_F16(acc[mt][nt], a, bf[nt]);
            }
        }
    }
#undef G2_LOAD

#pragma unroll
    for (int mt = 0; mt < 4; mt++) {
#pragma unroll
        for (int nt = 0; nt < 4; nt++) {
            int row = m0 + warpM * 64 + mt * 16 + g;
            int col = n0 + warpN * 32 + nt * 8 + 2 * tig;
            if (row < count) {
                __half2 v = __floats2half2_rn(acc[mt][nt][0], acc[mt][nt][1]);
                *(__half2*)(g_o2 + (size_t)(base + row) * H_DIM + col) = v;
            }
            if (row + 8 < count) {
                __half2 v = __floats2half2_rn(acc[mt][nt][2], acc[mt][nt][3]);
                *(__half2*)(g_o2 + (size_t)(base + row + 8) * H_DIM + col) = v;
            }
        }
    }
}

// ----------------------------- combine (fp16 gather, fp32 out) ---------------
__global__ void combine_kernel(float* __restrict__ out) {
    int idx = blockIdx.x * blockDim.x + threadIdx.x;   // T*H/8 threads
    int t = idx >> 8;            // H/8 = 256
    int c = (idx & 255) * 8;     // half offset within row
    const uint4* r0 = (const uint4*)(g_o2 + (size_t)g_slot[t * 2]     * H_DIM + c);
    const uint4* r1 = (const uint4*)(g_o2 + (size_t)g_slot[t * 2 + 1] * H_DIM + c);
    uint4 a = *r0, b = *r1;
    const __half2* ah = (const __half2*)&a;
    const __half2* bh = (const __half2*)&b;
    float4 o0, o1;
    float2 f, g2;
    f = __half22float2(ah[0]); g2 = __half22float2(bh[0]); o0.x = f.x + g2.x; o0.y = f.y + g2.y;
    f = __half22float2(ah[1]); g2 = __half22float2(bh[1]); o0.z = f.x + g2.x; o0.w = f.y + g2.y;
    f = __half22float2(ah[2]); g2 = __half22float2(bh[2]); o1.x = f.x + g2.x; o1.y = f.y + g2.y;
    f = __half22float2(ah[3]); g2 = __half22float2(bh[3]); o1.z = f.x + g2.x; o1.w = f.y + g2.y;
    float* op = out + (size_t)t * H_DIM + c;
    *(float4*)(op)     = o0;
    *(float4*)(op + 4) = o1;
}

// ----------------------------- launch -----------------------------------------
extern "C" void kernel_launch(void* const* d_in, const int* in_sizes, int n_in,
                              void* d_out, int out_size) {
    const float* x  = (const float*)d_in[0];
    const float* gw = (const float*)d_in[1];
    const float* W1 = (const float*)d_in[2];
    const float* Up = (const float*)d_in[3];
    const float* W2 = (const float*)d_in[4];
    float* out = (float*)d_out;

    const int SMEM1 = 3 * STG1_B;    // 110,592
    const int SMEM2 = 3 * STG2_B;    // 110,592
    cudaFuncSetAttribute(gemm1_mma, cudaFuncAttributeMaxDynamicSharedMemorySize, SMEM1);
    cudaFuncSetAttribute(gemm2_mma, cudaFuncAttributeMaxDynamicSharedMemorySize, SMEM2);

    prep_kernel<<<PREP_BLKS, 256>>>(x, gw, (const float4*)W1, (const float4*)Up); // 0
    scatter_kernel<<<1, 1024>>>();                                                // 1

    gemm1_mma<<<G1_BLOCKS, 256, SMEM1>>>((const float4*)W2);                      // 2

    gemm2_mma<<<MAX_TILES / 160 * 0 + 143 * 16, 256, SMEM2>>>();                  // 3: 2288 blocks

    combine_kernel<<<(T_TOK * H_DIM / 8) / 256, 256>>>(out);                      // 4
}